// round 10
// baseline (speedup 1.0000x reference)
#include <cuda_runtime.h>
#include <cuda_bf16.h>
#include <mma.h>
#include <cstdint>

using namespace nvcuda;

#define MAXN 100000
#define MAXE 1300000

// ---------------- scratch (static device globals; no allocations allowed) ----
__device__ float g_neigh[MAXN * 128];
__device__ float g_hA[MAXN * 128];
__device__ float g_hB[MAXN * 128];
__device__ int   g_cnt[MAXN];
__device__ int   g_rowptr[MAXN];
__device__ int   g_cursor[MAXN];
__device__ int   g_bsum[128];
__device__ int   g_eidx[MAXE];
__device__ float g_stats[256];   // [0:128) colsum, [128:256) colsumsq
__device__ float g_scale[128];
__device__ float g_shift[128];
__device__ __nv_bfloat16 g_WtB[128 * 256];  // W^T big part   [N=128][K<=256]
__device__ __nv_bfloat16 g_WtS[128 * 256];  // W^T small part

// ---------------- utility kernels -------------------------------------------
__global__ void zero_kernel(float4* p, int n4) {
    int i = blockIdx.x * blockDim.x + threadIdx.x;
    if (i < n4) p[i] = make_float4(0.f, 0.f, 0.f, 0.f);
}

// ---------------- CSR build --------------------------------------------------
__global__ void count_kernel(const int* __restrict__ dst, int* __restrict__ cnt, int E) {
    int e = blockIdx.x * blockDim.x + threadIdx.x;
    if (e < E) atomicAdd(&cnt[dst[e]], 1);
}

__global__ void scan1_kernel(const int* __restrict__ cnt, int* __restrict__ rowptr,
                             int* __restrict__ bsum, int n) {
    __shared__ int sdata[256];
    int b = blockIdx.x, t = threadIdx.x;
    int base = b * 2048 + t * 8;
    int v[8], s = 0;
#pragma unroll
    for (int i = 0; i < 8; i++) {
        int idx = base + i;
        v[i] = (idx < n) ? cnt[idx] : 0;
        s += v[i];
    }
    sdata[t] = s;
    __syncthreads();
    for (int off = 1; off < 256; off <<= 1) {
        int xv = (t >= off) ? sdata[t - off] : 0;
        __syncthreads();
        sdata[t] += xv;
        __syncthreads();
    }
    int run = sdata[t] - s;
    if (t == 255) bsum[b] = sdata[255];
#pragma unroll
    for (int i = 0; i < 8; i++) {
        int idx = base + i;
        if (idx < n) rowptr[idx] = run;
        run += v[i];
    }
}

__global__ void scan2_kernel(int* __restrict__ bsum, int nb) {
    if (threadIdx.x == 0) {
        int s = 0;
        for (int i = 0; i < nb; i++) { int t = bsum[i]; bsum[i] = s; s += t; }
    }
}

__global__ void scan3_kernel(int* __restrict__ rowptr, const int* __restrict__ bsum, int n) {
    int i = blockIdx.x * blockDim.x + threadIdx.x;
    if (i < n) rowptr[i] += bsum[i >> 11];
}

__global__ void fill_kernel(const int* __restrict__ src, const int* __restrict__ dst,
                            const int* __restrict__ rowptr, int* __restrict__ cursor,
                            int* __restrict__ eidx, int E) {
    int e = blockIdx.x * blockDim.x + threadIdx.x;
    if (e < E) {
        int d = dst[e];
        int p = atomicAdd(&cursor[d], 1);
        eidx[rowptr[d] + p] = src[e];
    }
}

// ---------------- mean aggregation via CSR gather (+ fused BN/ReLU) ----------
// One warp per node. If BN: each loaded element is relu(v*scale+shift) — the
// previous layer's BN/ReLU applied on the fly (saves a full elementwise pass).
template <int DIM, bool BN>
__global__ void gather_kernel(const float* __restrict__ x, const int* __restrict__ eidx,
                              const int* __restrict__ rowptr, const int* __restrict__ cnt,
                              const float* __restrict__ scale, const float* __restrict__ shift,
                              float* __restrict__ neigh, int n) {
    int node = blockIdx.x * (blockDim.x >> 5) + (threadIdx.x >> 5);
    int lane = threadIdx.x & 31;
    if (node >= n) return;
    int start = rowptr[node];
    int d = cnt[node];

    if (DIM == 128) {
        float4 sc, sh;
        if (BN) {
            sc = reinterpret_cast<const float4*>(scale)[lane];
            sh = reinterpret_cast<const float4*>(shift)[lane];
        }
        float4 a0 = make_float4(0.f, 0.f, 0.f, 0.f);
        float4 a1 = make_float4(0.f, 0.f, 0.f, 0.f);
        int j = 0;
        for (; j + 4 <= d; j += 4) {
            int s0 = eidx[start + j + 0];
            int s1 = eidx[start + j + 1];
            int s2 = eidx[start + j + 2];
            int s3 = eidx[start + j + 3];
            float4 v0 = *reinterpret_cast<const float4*>(x + (size_t)s0 * 128 + lane * 4);
            float4 v1 = *reinterpret_cast<const float4*>(x + (size_t)s1 * 128 + lane * 4);
            float4 v2 = *reinterpret_cast<const float4*>(x + (size_t)s2 * 128 + lane * 4);
            float4 v3 = *reinterpret_cast<const float4*>(x + (size_t)s3 * 128 + lane * 4);
            if (BN) {
                v0.x = fmaxf(fmaf(v0.x, sc.x, sh.x), 0.f); v0.y = fmaxf(fmaf(v0.y, sc.y, sh.y), 0.f);
                v0.z = fmaxf(fmaf(v0.z, sc.z, sh.z), 0.f); v0.w = fmaxf(fmaf(v0.w, sc.w, sh.w), 0.f);
                v1.x = fmaxf(fmaf(v1.x, sc.x, sh.x), 0.f); v1.y = fmaxf(fmaf(v1.y, sc.y, sh.y), 0.f);
                v1.z = fmaxf(fmaf(v1.z, sc.z, sh.z), 0.f); v1.w = fmaxf(fmaf(v1.w, sc.w, sh.w), 0.f);
                v2.x = fmaxf(fmaf(v2.x, sc.x, sh.x), 0.f); v2.y = fmaxf(fmaf(v2.y, sc.y, sh.y), 0.f);
                v2.z = fmaxf(fmaf(v2.z, sc.z, sh.z), 0.f); v2.w = fmaxf(fmaf(v2.w, sc.w, sh.w), 0.f);
                v3.x = fmaxf(fmaf(v3.x, sc.x, sh.x), 0.f); v3.y = fmaxf(fmaf(v3.y, sc.y, sh.y), 0.f);
                v3.z = fmaxf(fmaf(v3.z, sc.z, sh.z), 0.f); v3.w = fmaxf(fmaf(v3.w, sc.w, sh.w), 0.f);
            }
            a0.x += v0.x + v1.x; a0.y += v0.y + v1.y; a0.z += v0.z + v1.z; a0.w += v0.w + v1.w;
            a1.x += v2.x + v3.x; a1.y += v2.y + v3.y; a1.z += v2.z + v3.z; a1.w += v2.w + v3.w;
        }
        for (; j < d; j++) {
            int s = eidx[start + j];
            float4 v = *reinterpret_cast<const float4*>(x + (size_t)s * 128 + lane * 4);
            if (BN) {
                v.x = fmaxf(fmaf(v.x, sc.x, sh.x), 0.f); v.y = fmaxf(fmaf(v.y, sc.y, sh.y), 0.f);
                v.z = fmaxf(fmaf(v.z, sc.z, sh.z), 0.f); v.w = fmaxf(fmaf(v.w, sc.w, sh.w), 0.f);
            }
            a0.x += v.x; a0.y += v.y; a0.z += v.z; a0.w += v.w;
        }
        float inv = 1.0f / (float)max(d, 1);
        float4 o;
        o.x = (a0.x + a1.x) * inv; o.y = (a0.y + a1.y) * inv;
        o.z = (a0.z + a1.z) * inv; o.w = (a0.w + a1.w) * inv;
        *reinterpret_cast<float4*>(neigh + (size_t)node * 128 + lane * 4) = o;
    } else {  // DIM == 64 (layer 0: raw input, no BN)
        float2 a0 = make_float2(0.f, 0.f);
        float2 a1 = make_float2(0.f, 0.f);
        int j = 0;
        for (; j + 4 <= d; j += 4) {
            int s0 = eidx[start + j + 0];
            int s1 = eidx[start + j + 1];
            int s2 = eidx[start + j + 2];
            int s3 = eidx[start + j + 3];
            float2 v0 = *reinterpret_cast<const float2*>(x + (size_t)s0 * 64 + lane * 2);
            float2 v1 = *reinterpret_cast<const float2*>(x + (size_t)s1 * 64 + lane * 2);
            float2 v2 = *reinterpret_cast<const float2*>(x + (size_t)s2 * 64 + lane * 2);
            float2 v3 = *reinterpret_cast<const float2*>(x + (size_t)s3 * 64 + lane * 2);
            a0.x += v0.x + v1.x; a0.y += v0.y + v1.y;
            a1.x += v2.x + v3.x; a1.y += v2.y + v3.y;
        }
        for (; j < d; j++) {
            int s = eidx[start + j];
            float2 v = *reinterpret_cast<const float2*>(x + (size_t)s * 64 + lane * 2);
            a0.x += v.x; a0.y += v.y;
        }
        float inv = 1.0f / (float)max(d, 1);
        float2 o;
        o.x = (a0.x + a1.x) * inv; o.y = (a0.y + a1.y) * inv;
        *reinterpret_cast<float2*>(neigh + (size_t)node * 64 + lane * 2) = o;
    }
}

// ---------------- weight transpose + bf16 big/small split --------------------
__global__ void wsplit_kernel(const float* __restrict__ Ws, const float* __restrict__ Wn,
                              __nv_bfloat16* __restrict__ WtB,
                              __nv_bfloat16* __restrict__ WtS, int DIN) {
    int K = 2 * DIN;
    int idx = blockIdx.x * blockDim.x + threadIdx.x;
    if (idx >= 128 * K) return;
    int nrow = idx / K;
    int k = idx - nrow * K;
    float v = (k < DIN) ? Ws[k * 128 + nrow] : Wn[(k - DIN) * 128 + nrow];
    __nv_bfloat16 b = __float2bfloat16(v);
    float s = v - __bfloat162float(b);
    WtB[idx] = b;
    WtS[idx] = __float2bfloat16(s);
}

// ---------------- wmma bf16 GEMM + BN-stats (3-term split) -------------------
// If BN: the self-half A loads (from prev layer's raw h) get relu(v*sc+sh)
// applied in-register before the bf16 split (neigh half already normalized).
#define BKP 40                        // padded tile K-stride (bf16 elements)
#define OFF_AS  10240
#define OFF_BB  20480
#define OFF_BS  30720
#define OFF_ST  67584                 // after sD (128 * 132 * 4 = 67584)
#define OFF_ST2 68096
#define OFF_BI  68608
#define OFF_SC  69120
#define OFF_SH  69632
#define GEMM_SMEM 70144

template <int DIN, bool BN>
__global__ __launch_bounds__(256) void gemm_wmma_kernel(
    const float* __restrict__ x, const float* __restrict__ neigh,
    const __nv_bfloat16* __restrict__ WtB, const __nv_bfloat16* __restrict__ WtS,
    const float* __restrict__ bias, const float* __restrict__ scale,
    const float* __restrict__ shift, float* __restrict__ h,
    float* __restrict__ stats, int n) {
    constexpr int K = 2 * DIN;
    constexpr int NC = K / 32;

    extern __shared__ char sm[];
    __nv_bfloat16* sAB = (__nv_bfloat16*)(sm);
    __nv_bfloat16* sAS = (__nv_bfloat16*)(sm + OFF_AS);
    __nv_bfloat16* sBB = (__nv_bfloat16*)(sm + OFF_BB);
    __nv_bfloat16* sBS = (__nv_bfloat16*)(sm + OFF_BS);
    float* sD      = (float*)sm;              // [128][132] (epilogue overlay)
    float* sStats  = (float*)(sm + OFF_ST);
    float* sStats2 = (float*)(sm + OFF_ST2);
    float* sBias   = (float*)(sm + OFF_BI);
    float* sSc     = (float*)(sm + OFF_SC);
    float* sSh     = (float*)(sm + OFF_SH);

    int tid = threadIdx.x;
    int row0 = blockIdx.x * 128;
    if (tid < 128) {
        sStats[tid] = 0.f;
        sStats2[tid] = 0.f;
        sBias[tid] = bias[tid];
        if (BN) { sSc[tid] = scale[tid]; sSh[tid] = shift[tid]; }
    }
    __syncthreads();

    int w = tid >> 5;
    int wm = w & 1;    // rows wm*64 .. +63
    int wn = w >> 1;   // cols wn*32 .. +31

    wmma::fragment<wmma::accumulator, 16, 16, 16, float> acc[4][2];
#pragma unroll
    for (int i = 0; i < 4; i++)
#pragma unroll
        for (int j = 0; j < 2; j++) wmma::fill_fragment(acc[i][j], 0.f);

    for (int c = 0; c < NC; c++) {
        bool isSelf = (c * 32 < DIN);
        const float* Asrc = isSelf ? x : neigh;
        int koff = isSelf ? c * 32 : c * 32 - DIN;

        // ---- A tile: 128 rows x 32 f32, (BN on self half), split bf16 ----
#pragma unroll
        for (int i = 0; i < 4; i++) {
            int f = tid + i * 256;       // 0..1023 quads
            int row = f >> 3;
            int q = f & 7;               // float4 index along k
            int grow = row0 + row;
            float4 v = make_float4(0.f, 0.f, 0.f, 0.f);
            if (grow < n)
                v = *reinterpret_cast<const float4*>(Asrc + (size_t)grow * DIN + koff + q * 4);
            if (BN && isSelf) {
                int kc = koff + q * 4;
                v.x = fmaxf(fmaf(v.x, sSc[kc + 0], sSh[kc + 0]), 0.f);
                v.y = fmaxf(fmaf(v.y, sSc[kc + 1], sSh[kc + 1]), 0.f);
                v.z = fmaxf(fmaf(v.z, sSc[kc + 2], sSh[kc + 2]), 0.f);
                v.w = fmaxf(fmaf(v.w, sSc[kc + 3], sSh[kc + 3]), 0.f);
            }
            __nv_bfloat16 b0 = __float2bfloat16(v.x), b1 = __float2bfloat16(v.y);
            __nv_bfloat16 b2 = __float2bfloat16(v.z), b3 = __float2bfloat16(v.w);
            __nv_bfloat16 s0 = __float2bfloat16(v.x - __bfloat162float(b0));
            __nv_bfloat16 s1 = __float2bfloat16(v.y - __bfloat162float(b1));
            __nv_bfloat16 s2 = __float2bfloat16(v.z - __bfloat162float(b2));
            __nv_bfloat16 s3 = __float2bfloat16(v.w - __bfloat162float(b3));
            int o = row * BKP + q * 4;
            *reinterpret_cast<__nv_bfloat162*>(sAB + o)     = __nv_bfloat162(b0, b1);
            *reinterpret_cast<__nv_bfloat162*>(sAB + o + 2) = __nv_bfloat162(b2, b3);
            *reinterpret_cast<__nv_bfloat162*>(sAS + o)     = __nv_bfloat162(s0, s1);
            *reinterpret_cast<__nv_bfloat162*>(sAS + o + 2) = __nv_bfloat162(s2, s3);
        }
        // ---- B tile: 128 N-rows x 32 bf16 from pre-split Wt (16B chunks) ----
#pragma unroll
        for (int i = 0; i < 2; i++) {
            int f = tid + i * 256;       // 0..511 oct-groups
            int row = f >> 2;
            int q = f & 3;               // 8-bf16 group along k
            const uint4* pb = reinterpret_cast<const uint4*>(WtB + (size_t)row * K + c * 32 + q * 8);
            const uint4* ps = reinterpret_cast<const uint4*>(WtS + (size_t)row * K + c * 32 + q * 8);
            *reinterpret_cast<uint4*>(sBB + row * BKP + q * 8) = *pb;
            *reinterpret_cast<uint4*>(sBS + row * BKP + q * 8) = *ps;
        }
        __syncthreads();

#pragma unroll
        for (int ks = 0; ks < 2; ks++) {
            int kk = ks * 16;
            wmma::fragment<wmma::matrix_b, 16, 16, 16, __nv_bfloat16, wmma::col_major> fbB[2], fbS[2];
#pragma unroll
            for (int j = 0; j < 2; j++) {
                wmma::load_matrix_sync(fbB[j], sBB + (wn * 32 + j * 16) * BKP + kk, BKP);
                wmma::load_matrix_sync(fbS[j], sBS + (wn * 32 + j * 16) * BKP + kk, BKP);
            }
#pragma unroll
            for (int i = 0; i < 4; i++) {
                wmma::fragment<wmma::matrix_a, 16, 16, 16, __nv_bfloat16, wmma::row_major> faB, faS;
                wmma::load_matrix_sync(faB, sAB + (wm * 64 + i * 16) * BKP + kk, BKP);
                wmma::load_matrix_sync(faS, sAS + (wm * 64 + i * 16) * BKP + kk, BKP);
#pragma unroll
                for (int j = 0; j < 2; j++) {
                    wmma::mma_sync(acc[i][j], faB, fbB[j], acc[i][j]);
                    wmma::mma_sync(acc[i][j], faB, fbS[j], acc[i][j]);
                    wmma::mma_sync(acc[i][j], faS, fbB[j], acc[i][j]);
                }
            }
        }
        __syncthreads();
    }

    // ---- epilogue: fragments -> smem (stride 132), +bias, h stores, stats ----
#pragma unroll
    for (int i = 0; i < 4; i++)
#pragma unroll
        for (int j = 0; j < 2; j++)
            wmma::store_matrix_sync(sD + (wm * 64 + i * 16) * 132 + wn * 32 + j * 16,
                                    acc[i][j], 132, wmma::mem_row_major);
    __syncthreads();
    {
        int cq = tid & 31;   // column quad: cols cq*4 .. +3
        int wr = tid >> 5;   // row stride-8 phase
        float4 bi = *reinterpret_cast<const float4*>(sBias + cq * 4);
        float ps0 = 0.f, ps1 = 0.f, ps2 = 0.f, ps3 = 0.f;
        float pq0 = 0.f, pq1 = 0.f, pq2 = 0.f, pq3 = 0.f;
#pragma unroll
        for (int it = 0; it < 16; it++) {
            int r = wr + it * 8;
            int grow = row0 + r;
            if (grow < n) {
                float v0 = sD[r * 132 + cq * 4 + 0] + bi.x;
                float v1 = sD[r * 132 + cq * 4 + 1] + bi.y;
                float v2 = sD[r * 132 + cq * 4 + 2] + bi.z;
                float v3 = sD[r * 132 + cq * 4 + 3] + bi.w;
                *reinterpret_cast<float4*>(h + (size_t)grow * 128 + cq * 4) =
                    make_float4(v0, v1, v2, v3);
                ps0 += v0; ps1 += v1; ps2 += v2; ps3 += v3;
                pq0 += v0 * v0; pq1 += v1 * v1; pq2 += v2 * v2; pq3 += v3 * v3;
            }
        }
        atomicAdd(&sStats[cq * 4 + 0], ps0); atomicAdd(&sStats2[cq * 4 + 0], pq0);
        atomicAdd(&sStats[cq * 4 + 1], ps1); atomicAdd(&sStats2[cq * 4 + 1], pq1);
        atomicAdd(&sStats[cq * 4 + 2], ps2); atomicAdd(&sStats2[cq * 4 + 2], pq2);
        atomicAdd(&sStats[cq * 4 + 3], ps3); atomicAdd(&sStats2[cq * 4 + 3], pq3);
    }
    __syncthreads();
    if (tid < 128) {
        atomicAdd(&stats[tid], sStats[tid]);
        atomicAdd(&stats[128 + tid], sStats2[tid]);
    }
}

// ---------------- BN parameter folding (also resets stats for next layer) ----
__global__ void bnparam_kernel(float* __restrict__ stats, const float* __restrict__ gamma,
                               const float* __restrict__ beta, float* __restrict__ scale,
                               float* __restrict__ shift, float invN) {
    int j = threadIdx.x;
    float mu = stats[j] * invN;
    float var = stats[128 + j] * invN - mu * mu;
    float sc = gamma[j] * rsqrtf(var + 1e-5f);
    scale[j] = sc;
    shift[j] = fmaf(-mu, sc, beta[j]);
    stats[j] = 0.f;          // re-zero accumulator for the next layer
    stats[128 + j] = 0.f;
}

// ---------------- fused BN + ReLU + classifier (final layer) ----------------
__global__ void bn_cls_kernel(const float* __restrict__ h, const float* __restrict__ scale,
                              const float* __restrict__ shift, const float* __restrict__ Wc,
                              const float* __restrict__ bc, float* __restrict__ out, int n) {
    int warp = (blockIdx.x * blockDim.x + threadIdx.x) >> 5;
    int lane = threadIdx.x & 31;
    if (warp >= n) return;
    float4 v = reinterpret_cast<const float4*>(h + (size_t)warp * 128)[lane];
    float4 sc = reinterpret_cast<const float4*>(scale)[lane];
    float4 sh = reinterpret_cast<const float4*>(shift)[lane];
    int c = lane * 4;
    float w0 = fmaxf(fmaf(v.x, sc.x, sh.x), 0.f);
    float w1 = fmaxf(fmaf(v.y, sc.y, sh.y), 0.f);
    float w2 = fmaxf(fmaf(v.z, sc.z, sh.z), 0.f);
    float w3 = fmaxf(fmaf(v.w, sc.w, sh.w), 0.f);
    float a0 = w0 * Wc[(c + 0) * 2 + 0] + w1 * Wc[(c + 1) * 2 + 0] +
               w2 * Wc[(c + 2) * 2 + 0] + w3 * Wc[(c + 3) * 2 + 0];
    float a1 = w0 * Wc[(c + 0) * 2 + 1] + w1 * Wc[(c + 1) * 2 + 1] +
               w2 * Wc[(c + 2) * 2 + 1] + w3 * Wc[(c + 3) * 2 + 1];
#pragma unroll
    for (int off = 16; off; off >>= 1) {
        a0 += __shfl_xor_sync(0xffffffffu, a0, off);
        a1 += __shfl_xor_sync(0xffffffffu, a1, off);
    }
    if (lane == 0) {
        out[(size_t)warp * 2 + 0] = a0 + bc[0];
        out[(size_t)warp * 2 + 1] = a1 + bc[1];
    }
}

// ---------------- host entry -------------------------------------------------
extern "C" void kernel_launch(void* const* d_in, const int* in_sizes, int n_in,
                              void* d_out, int out_size) {
    const float* x = (const float*)d_in[0];
    const int* src = (const int*)d_in[1];
    const int* dst = (const int*)d_in[2];
    const float* Ws0 = (const float*)d_in[3];
    const float* b0 = (const float*)d_in[4];
    const float* Wn0 = (const float*)d_in[5];
    const float* g0 = (const float*)d_in[6];
    const float* be0 = (const float*)d_in[7];
    const float* Ws1 = (const float*)d_in[8];
    const float* b1 = (const float*)d_in[9];
    const float* Wn1 = (const float*)d_in[10];
    const float* g1 = (const float*)d_in[11];
    const float* be1 = (const float*)d_in[12];
    const float* Ws2 = (const float*)d_in[13];
    const float* b2 = (const float*)d_in[14];
    const float* Wn2 = (const float*)d_in[15];
    const float* g2 = (const float*)d_in[16];
    const float* be2 = (const float*)d_in[17];
    const float* Wc = (const float*)d_in[18];
    const float* bc = (const float*)d_in[19];
    float* out = (float*)d_out;

    int n = in_sizes[0] / 64;
    int E = in_sizes[1];
    float invN = 1.0f / (float)n;

    float *neigh, *hA, *hB, *stats, *scale, *shift;
    __nv_bfloat16 *WtB, *WtS;
    int *cnt, *rowptr, *cursor, *bsum, *eidx;
    cudaGetSymbolAddress((void**)&neigh, g_neigh);
    cudaGetSymbolAddress((void**)&hA, g_hA);
    cudaGetSymbolAddress((void**)&hB, g_hB);
    cudaGetSymbolAddress((void**)&cnt, g_cnt);
    cudaGetSymbolAddress((void**)&rowptr, g_rowptr);
    cudaGetSymbolAddress((void**)&cursor, g_cursor);
    cudaGetSymbolAddress((void**)&bsum, g_bsum);
    cudaGetSymbolAddress((void**)&eidx, g_eidx);
    cudaGetSymbolAddress((void**)&stats, g_stats);
    cudaGetSymbolAddress((void**)&scale, g_scale);
    cudaGetSymbolAddress((void**)&shift, g_shift);
    cudaGetSymbolAddress((void**)&WtB, g_WtB);
    cudaGetSymbolAddress((void**)&WtS, g_WtS);

    cudaFuncSetAttribute(gemm_wmma_kernel<64, false>,
                         cudaFuncAttributeMaxDynamicSharedMemorySize, GEMM_SMEM);
    cudaFuncSetAttribute(gemm_wmma_kernel<128, true>,
                         cudaFuncAttributeMaxDynamicSharedMemorySize, GEMM_SMEM);

    const int T = 256;
    int gb = (n + 127) / 128;
    int nb = (n + 2047) / 2048;
    int gwarp = (n + 7) / 8;

    // ---- CSR build (once, reused by all 3 layers) ----
    zero_kernel<<<(n / 4 + T - 1) / T, T>>>((float4*)cnt, n / 4);
    zero_kernel<<<(n / 4 + T - 1) / T, T>>>((float4*)cursor, n / 4);
    zero_kernel<<<1, 64>>>((float4*)stats, 64);   // once; bnparam re-zeros after
    count_kernel<<<(E + T - 1) / T, T>>>(dst, cnt, E);
    scan1_kernel<<<nb, 256>>>(cnt, rowptr, bsum, n);
    scan2_kernel<<<1, 32>>>(bsum, nb);
    scan3_kernel<<<(n + T - 1) / T, T>>>(rowptr, bsum, n);
    fill_kernel<<<(E + T - 1) / T, T>>>(src, dst, rowptr, cursor, eidx, E);

    // ---- layer 0 (DIN = 64, raw input, no BN on loads) ----
    wsplit_kernel<<<(128 * 128 + T - 1) / T, T>>>(Ws0, Wn0, WtB, WtS, 64);
    gather_kernel<64, false><<<gwarp, T>>>(x, eidx, rowptr, cnt, scale, shift, neigh, n);
    gemm_wmma_kernel<64, false><<<gb, T, GEMM_SMEM>>>(x, neigh, WtB, WtS, b0,
                                                      scale, shift, hA, stats, n);
    bnparam_kernel<<<1, 128>>>(stats, g0, be0, scale, shift, invN);

    // ---- layer 1 (DIN = 128, BN/ReLU of layer 0 fused into loads) ----
    wsplit_kernel<<<(128 * 256 + T - 1) / T, T>>>(Ws1, Wn1, WtB, WtS, 128);
    gather_kernel<128, true><<<gwarp, T>>>(hA, eidx, rowptr, cnt, scale, shift, neigh, n);
    gemm_wmma_kernel<128, true><<<gb, T, GEMM_SMEM>>>(hA, neigh, WtB, WtS, b1,
                                                      scale, shift, hB, stats, n);
    bnparam_kernel<<<1, 128>>>(stats, g1, be1, scale, shift, invN);

    // ---- layer 2 (DIN = 128) + fused BN/ReLU/classifier ----
    wsplit_kernel<<<(128 * 256 + T - 1) / T, T>>>(Ws2, Wn2, WtB, WtS, 128);
    gather_kernel<128, true><<<gwarp, T>>>(hB, eidx, rowptr, cnt, scale, shift, neigh, n);
    gemm_wmma_kernel<128, true><<<gb, T, GEMM_SMEM>>>(hB, neigh, WtB, WtS, b2,
                                                      scale, shift, hA, stats, n);
    bnparam_kernel<<<1, 128>>>(stats, g2, be2, scale, shift, invN);
    bn_cls_kernel<<<(n * 32 + T - 1) / T, T>>>(hA, scale, shift, Wc, bc, out, n);
}

// round 14
// speedup vs baseline: 1.0389x; 1.0389x over previous
#include <cuda_runtime.h>
#include <cuda_bf16.h>
#include <mma.h>
#include <cstdint>

using namespace nvcuda;

#define MAXN 100000
#define MAXE 1300000

// ---------------- scratch (static device globals; no allocations allowed) ----
__device__ float g_neigh[MAXN * 128];
__device__ float g_h[MAXN * 128];
__device__ float g_xA[MAXN * 128];
__device__ float g_xB[MAXN * 128];
__device__ int   g_cnt[MAXN];
__device__ int   g_rowptr[MAXN];
__device__ int   g_cursor[MAXN];
__device__ int   g_bsum[128];
__device__ int   g_eidx[MAXE];
__device__ float g_stats[256];   // [0:128) colsum, [128:256) colsumsq
__device__ float g_scale[128];
__device__ float g_shift[128];
__device__ __nv_bfloat16 g_WtB[128 * 256];  // W^T big part   [N=128][K<=256]
__device__ __nv_bfloat16 g_WtS[128 * 256];  // W^T small part

// ---------------- utility kernels -------------------------------------------
__global__ void zero_kernel(float4* p, int n4) {
    int i = blockIdx.x * blockDim.x + threadIdx.x;
    if (i < n4) p[i] = make_float4(0.f, 0.f, 0.f, 0.f);
}

__global__ void zero2_kernel(float4* a, float4* b, int n4) {
    int i = blockIdx.x * blockDim.x + threadIdx.x;
    if (i < n4) {
        a[i] = make_float4(0.f, 0.f, 0.f, 0.f);
        b[i] = make_float4(0.f, 0.f, 0.f, 0.f);
    }
}

// ---------------- CSR build --------------------------------------------------
__global__ void count_kernel(const int* __restrict__ dst, int* __restrict__ cnt, int E) {
    int e = blockIdx.x * blockDim.x + threadIdx.x;
    if (e < E) atomicAdd(&cnt[dst[e]], 1);
}

__global__ void scan1_kernel(const int* __restrict__ cnt, int* __restrict__ rowptr,
                             int* __restrict__ bsum, int n) {
    __shared__ int sdata[256];
    int b = blockIdx.x, t = threadIdx.x;
    int base = b * 2048 + t * 8;
    int v[8], s = 0;
#pragma unroll
    for (int i = 0; i < 8; i++) {
        int idx = base + i;
        v[i] = (idx < n) ? cnt[idx] : 0;
        s += v[i];
    }
    sdata[t] = s;
    __syncthreads();
    for (int off = 1; off < 256; off <<= 1) {
        int xv = (t >= off) ? sdata[t - off] : 0;
        __syncthreads();
        sdata[t] += xv;
        __syncthreads();
    }
    int run = sdata[t] - s;
    if (t == 255) bsum[b] = sdata[255];
#pragma unroll
    for (int i = 0; i < 8; i++) {
        int idx = base + i;
        if (idx < n) rowptr[idx] = run;
        run += v[i];
    }
}

__global__ void scan2_kernel(int* __restrict__ bsum, int nb) {
    if (threadIdx.x == 0) {
        int s = 0;
        for (int i = 0; i < nb; i++) { int t = bsum[i]; bsum[i] = s; s += t; }
    }
}

__global__ void scan3_kernel(int* __restrict__ rowptr, const int* __restrict__ bsum, int n) {
    int i = blockIdx.x * blockDim.x + threadIdx.x;
    if (i < n) rowptr[i] += bsum[i >> 11];
}

__global__ void fill_kernel(const int* __restrict__ src, const int* __restrict__ dst,
                            const int* __restrict__ rowptr, int* __restrict__ cursor,
                            int* __restrict__ eidx, int E) {
    int e = blockIdx.x * blockDim.x + threadIdx.x;
    if (e < E) {
        int d = dst[e];
        int p = atomicAdd(&cursor[d], 1);
        eidx[rowptr[d] + p] = src[e];
    }
}

// ---------------- mean aggregation via CSR gather (LEAN — R10 lesson) --------
template <int DIM>
__global__ void gather_kernel(const float* __restrict__ x, const int* __restrict__ eidx,
                              const int* __restrict__ rowptr, const int* __restrict__ cnt,
                              float* __restrict__ neigh, int n) {
    int node = blockIdx.x * (blockDim.x >> 5) + (threadIdx.x >> 5);
    int lane = threadIdx.x & 31;
    if (node >= n) return;
    int start = rowptr[node];
    int d = cnt[node];

    if (DIM == 128) {
        float4 a0 = make_float4(0.f, 0.f, 0.f, 0.f);
        float4 a1 = make_float4(0.f, 0.f, 0.f, 0.f);
        int j = 0;
        for (; j + 4 <= d; j += 4) {
            int s0 = eidx[start + j + 0];
            int s1 = eidx[start + j + 1];
            int s2 = eidx[start + j + 2];
            int s3 = eidx[start + j + 3];
            float4 v0 = *reinterpret_cast<const float4*>(x + (size_t)s0 * 128 + lane * 4);
            float4 v1 = *reinterpret_cast<const float4*>(x + (size_t)s1 * 128 + lane * 4);
            float4 v2 = *reinterpret_cast<const float4*>(x + (size_t)s2 * 128 + lane * 4);
            float4 v3 = *reinterpret_cast<const float4*>(x + (size_t)s3 * 128 + lane * 4);
            a0.x += v0.x + v1.x; a0.y += v0.y + v1.y; a0.z += v0.z + v1.z; a0.w += v0.w + v1.w;
            a1.x += v2.x + v3.x; a1.y += v2.y + v3.y; a1.z += v2.z + v3.z; a1.w += v2.w + v3.w;
        }
        for (; j < d; j++) {
            int s = eidx[start + j];
            float4 v = *reinterpret_cast<const float4*>(x + (size_t)s * 128 + lane * 4);
            a0.x += v.x; a0.y += v.y; a0.z += v.z; a0.w += v.w;
        }
        float inv = 1.0f / (float)max(d, 1);
        float4 o;
        o.x = (a0.x + a1.x) * inv; o.y = (a0.y + a1.y) * inv;
        o.z = (a0.z + a1.z) * inv; o.w = (a0.w + a1.w) * inv;
        *reinterpret_cast<float4*>(neigh + (size_t)node * 128 + lane * 4) = o;
    } else {  // DIM == 64
        float2 a0 = make_float2(0.f, 0.f);
        float2 a1 = make_float2(0.f, 0.f);
        int j = 0;
        for (; j + 4 <= d; j += 4) {
            int s0 = eidx[start + j + 0];
            int s1 = eidx[start + j + 1];
            int s2 = eidx[start + j + 2];
            int s3 = eidx[start + j + 3];
            float2 v0 = *reinterpret_cast<const float2*>(x + (size_t)s0 * 64 + lane * 2);
            float2 v1 = *reinterpret_cast<const float2*>(x + (size_t)s1 * 64 + lane * 2);
            float2 v2 = *reinterpret_cast<const float2*>(x + (size_t)s2 * 64 + lane * 2);
            float2 v3 = *reinterpret_cast<const float2*>(x + (size_t)s3 * 64 + lane * 2);
            a0.x += v0.x + v1.x; a0.y += v0.y + v1.y;
            a1.x += v2.x + v3.x; a1.y += v2.y + v3.y;
        }
        for (; j < d; j++) {
            int s = eidx[start + j];
            float2 v = *reinterpret_cast<const float2*>(x + (size_t)s * 64 + lane * 2);
            a0.x += v.x; a0.y += v.y;
        }
        float inv = 1.0f / (float)max(d, 1);
        float2 o;
        o.x = (a0.x + a1.x) * inv; o.y = (a0.y + a1.y) * inv;
        *reinterpret_cast<float2*>(neigh + (size_t)node * 64 + lane * 2) = o;
    }
}

// ---------------- weight transpose + bf16 big/small split --------------------
__global__ void wsplit_kernel(const float* __restrict__ Ws, const float* __restrict__ Wn,
                              __nv_bfloat16* __restrict__ WtB,
                              __nv_bfloat16* __restrict__ WtS, int DIN) {
    int K = 2 * DIN;
    int idx = blockIdx.x * blockDim.x + threadIdx.x;
    if (idx >= 128 * K) return;
    int nrow = idx / K;
    int k = idx - nrow * K;
    float v = (k < DIN) ? Ws[k * 128 + nrow] : Wn[(k - DIN) * 128 + nrow];
    __nv_bfloat16 b = __float2bfloat16(v);
    float s = v - __bfloat162float(b);
    WtB[idx] = b;
    WtS[idx] = __float2bfloat16(s);
}

// ---------------- wmma bf16 GEMM + BN-stats (3-term split, pipelined) --------
// 2-stage register pipeline: chunk c+1's global loads are issued before chunk
// c's MMAs, hiding global latency behind tensor work.
#define BKP 40                        // padded tile K-stride (bf16 elements)
#define OFF_AS  10240
#define OFF_BB  20480
#define OFF_BS  30720
#define OFF_ST  67584                 // after sD (128 * 132 * 4 = 67584)
#define OFF_ST2 68096
#define OFF_BI  68608
#define GEMM_SMEM 69120

template <int DIN>
__global__ __launch_bounds__(256) void gemm_wmma_kernel(
    const float* __restrict__ x, const float* __restrict__ neigh,
    const __nv_bfloat16* __restrict__ WtB, const __nv_bfloat16* __restrict__ WtS,
    const float* __restrict__ bias, float* __restrict__ h,
    float* __restrict__ stats, int n) {
    constexpr int K = 2 * DIN;
    constexpr int NC = K / 32;

    extern __shared__ char sm[];
    __nv_bfloat16* sAB = (__nv_bfloat16*)(sm);
    __nv_bfloat16* sAS = (__nv_bfloat16*)(sm + OFF_AS);
    __nv_bfloat16* sBB = (__nv_bfloat16*)(sm + OFF_BB);
    __nv_bfloat16* sBS = (__nv_bfloat16*)(sm + OFF_BS);
    float* sD      = (float*)sm;              // [128][132] (epilogue overlay)
    float* sStats  = (float*)(sm + OFF_ST);
    float* sStats2 = (float*)(sm + OFF_ST2);
    float* sBias   = (float*)(sm + OFF_BI);

    int tid = threadIdx.x;
    int row0 = blockIdx.x * 128;
    if (tid < 128) {
        sStats[tid] = 0.f;
        sStats2[tid] = 0.f;
        sBias[tid] = bias[tid];
    }

    int w = tid >> 5;
    int wm = w & 1;    // rows wm*64 .. +63
    int wn = w >> 1;   // cols wn*32 .. +31

    // A-load indexing (4 float4 per thread per chunk)
    int a_row[4], a_q[4];
    bool a_ok[4];
#pragma unroll
    for (int i = 0; i < 4; i++) {
        int f = tid + i * 256;
        a_row[i] = f >> 3;
        a_q[i] = f & 7;
        a_ok[i] = (row0 + a_row[i]) < n;
    }
    // B-load indexing (2 uint4 per thread per chunk)
    int b_row[2], b_q[2];
#pragma unroll
    for (int i = 0; i < 2; i++) {
        int f = tid + i * 256;
        b_row[i] = f >> 2;
        b_q[i] = f & 3;
    }

    wmma::fragment<wmma::accumulator, 16, 16, 16, float> acc[4][2];
#pragma unroll
    for (int i = 0; i < 4; i++)
#pragma unroll
        for (int j = 0; j < 2; j++) wmma::fill_fragment(acc[i][j], 0.f);

    float4 va[4];
    uint4 vbB[2], vbS[2];

    // ---- prologue: load chunk 0 into registers ----
    {
        const float* Asrc = (0 < DIN) ? x : neigh;
#pragma unroll
        for (int i = 0; i < 4; i++) {
            va[i] = make_float4(0.f, 0.f, 0.f, 0.f);
            if (a_ok[i])
                va[i] = *reinterpret_cast<const float4*>(
                    Asrc + (size_t)(row0 + a_row[i]) * DIN + a_q[i] * 4);
        }
#pragma unroll
        for (int i = 0; i < 2; i++) {
            vbB[i] = *reinterpret_cast<const uint4*>(WtB + (size_t)b_row[i] * K + b_q[i] * 8);
            vbS[i] = *reinterpret_cast<const uint4*>(WtS + (size_t)b_row[i] * K + b_q[i] * 8);
        }
    }

    for (int c = 0; c < NC; c++) {
        // ---- convert current regs -> smem (big/small split) ----
#pragma unroll
        for (int i = 0; i < 4; i++) {
            float4 v = va[i];
            __nv_bfloat16 b0 = __float2bfloat16(v.x), b1 = __float2bfloat16(v.y);
            __nv_bfloat16 b2 = __float2bfloat16(v.z), b3 = __float2bfloat16(v.w);
            __nv_bfloat16 s0 = __float2bfloat16(v.x - __bfloat162float(b0));
            __nv_bfloat16 s1 = __float2bfloat16(v.y - __bfloat162float(b1));
            __nv_bfloat16 s2 = __float2bfloat16(v.z - __bfloat162float(b2));
            __nv_bfloat16 s3 = __float2bfloat16(v.w - __bfloat162float(b3));
            int o = a_row[i] * BKP + a_q[i] * 4;
            *reinterpret_cast<__nv_bfloat162*>(sAB + o)     = __nv_bfloat162(b0, b1);
            *reinterpret_cast<__nv_bfloat162*>(sAB + o + 2) = __nv_bfloat162(b2, b3);
            *reinterpret_cast<__nv_bfloat162*>(sAS + o)     = __nv_bfloat162(s0, s1);
            *reinterpret_cast<__nv_bfloat162*>(sAS + o + 2) = __nv_bfloat162(s2, s3);
        }
#pragma unroll
        for (int i = 0; i < 2; i++) {
            *reinterpret_cast<uint4*>(sBB + b_row[i] * BKP + b_q[i] * 8) = vbB[i];
            *reinterpret_cast<uint4*>(sBS + b_row[i] * BKP + b_q[i] * 8) = vbS[i];
        }
        __syncthreads();

        // ---- issue next chunk's global loads (consumed next iteration) ----
        if (c + 1 < NC) {
            int c1 = c + 1;
            bool isSelf = (c1 * 32 < DIN);
            const float* Asrc = isSelf ? x : neigh;
            int koff = isSelf ? c1 * 32 : c1 * 32 - DIN;
#pragma unroll
            for (int i = 0; i < 4; i++) {
                va[i] = make_float4(0.f, 0.f, 0.f, 0.f);
                if (a_ok[i])
                    va[i] = *reinterpret_cast<const float4*>(
                        Asrc + (size_t)(row0 + a_row[i]) * DIN + koff + a_q[i] * 4);
            }
#pragma unroll
            for (int i = 0; i < 2; i++) {
                vbB[i] = *reinterpret_cast<const uint4*>(
                    WtB + (size_t)b_row[i] * K + c1 * 32 + b_q[i] * 8);
                vbS[i] = *reinterpret_cast<const uint4*>(
                    WtS + (size_t)b_row[i] * K + c1 * 32 + b_q[i] * 8);
            }
        }

        // ---- MMAs on the smem tiles (overlaps the in-flight loads) ----
#pragma unroll
        for (int ks = 0; ks < 2; ks++) {
            int kk = ks * 16;
            wmma::fragment<wmma::matrix_b, 16, 16, 16, __nv_bfloat16, wmma::col_major> fbB[2], fbS[2];
#pragma unroll
            for (int j = 0; j < 2; j++) {
                wmma::load_matrix_sync(fbB[j], sBB + (wn * 32 + j * 16) * BKP + kk, BKP);
                wmma::load_matrix_sync(fbS[j], sBS + (wn * 32 + j * 16) * BKP + kk, BKP);
            }
#pragma unroll
            for (int i = 0; i < 4; i++) {
                wmma::fragment<wmma::matrix_a, 16, 16, 16, __nv_bfloat16, wmma::row_major> faB, faS;
                wmma::load_matrix_sync(faB, sAB + (wm * 64 + i * 16) * BKP + kk, BKP);
                wmma::load_matrix_sync(faS, sAS + (wm * 64 + i * 16) * BKP + kk, BKP);
#pragma unroll
                for (int j = 0; j < 2; j++) {
                    wmma::mma_sync(acc[i][j], faB, fbB[j], acc[i][j]);
                    wmma::mma_sync(acc[i][j], faB, fbS[j], acc[i][j]);
                    wmma::mma_sync(acc[i][j], faS, fbB[j], acc[i][j]);
                }
            }
        }
        __syncthreads();
    }

    // ---- epilogue: fragments -> smem (stride 132), +bias, h stores, stats ----
#pragma unroll
    for (int i = 0; i < 4; i++)
#pragma unroll
        for (int j = 0; j < 2; j++)
            wmma::store_matrix_sync(sD + (wm * 64 + i * 16) * 132 + wn * 32 + j * 16,
                                    acc[i][j], 132, wmma::mem_row_major);
    __syncthreads();
    {
        int cq = tid & 31;   // column quad: cols cq*4 .. +3
        int wr = tid >> 5;   // row stride-8 phase
        float4 bi = *reinterpret_cast<const float4*>(sBias + cq * 4);
        float ps0 = 0.f, ps1 = 0.f, ps2 = 0.f, ps3 = 0.f;
        float pq0 = 0.f, pq1 = 0.f, pq2 = 0.f, pq3 = 0.f;
#pragma unroll
        for (int it = 0; it < 16; it++) {
            int r = wr + it * 8;
            int grow = row0 + r;
            if (grow < n) {
                float v0 = sD[r * 132 + cq * 4 + 0] + bi.x;
                float v1 = sD[r * 132 + cq * 4 + 1] + bi.y;
                float v2 = sD[r * 132 + cq * 4 + 2] + bi.z;
                float v3 = sD[r * 132 + cq * 4 + 3] + bi.w;
                *reinterpret_cast<float4*>(h + (size_t)grow * 128 + cq * 4) =
                    make_float4(v0, v1, v2, v3);
                ps0 += v0; ps1 += v1; ps2 += v2; ps3 += v3;
                pq0 += v0 * v0; pq1 += v1 * v1; pq2 += v2 * v2; pq3 += v3 * v3;
            }
        }
        atomicAdd(&sStats[cq * 4 + 0], ps0); atomicAdd(&sStats2[cq * 4 + 0], pq0);
        atomicAdd(&sStats[cq * 4 + 1], ps1); atomicAdd(&sStats2[cq * 4 + 1], pq1);
        atomicAdd(&sStats[cq * 4 + 2], ps2); atomicAdd(&sStats2[cq * 4 + 2], pq2);
        atomicAdd(&sStats[cq * 4 + 3], ps3); atomicAdd(&sStats2[cq * 4 + 3], pq3);
    }
    __syncthreads();
    if (tid < 128) {
        atomicAdd(&stats[tid], sStats[tid]);
        atomicAdd(&stats[128 + tid], sStats2[tid]);
    }
}

// ---------------- BN parameter folding (also resets stats for next layer) ----
__global__ void bnparam_kernel(float* __restrict__ stats, const float* __restrict__ gamma,
                               const float* __restrict__ beta, float* __restrict__ scale,
                               float* __restrict__ shift, float invN) {
    int j = threadIdx.x;
    float mu = stats[j] * invN;
    float var = stats[128 + j] * invN - mu * mu;
    float sc = gamma[j] * rsqrtf(var + 1e-5f);
    scale[j] = sc;
    shift[j] = fmaf(-mu, sc, beta[j]);
    stats[j] = 0.f;
    stats[128 + j] = 0.f;
}

// ---------------- BN apply + ReLU (elementwise, float4) ---------------------
__global__ void bn_relu_kernel(const float* __restrict__ h, const float* __restrict__ scale,
                               const float* __restrict__ shift, float* __restrict__ out, int n) {
    int idx = blockIdx.x * blockDim.x + threadIdx.x;
    if (idx >= n * 32) return;
    int j4 = idx & 31;
    float4 v = reinterpret_cast<const float4*>(h)[idx];
    float4 sc = reinterpret_cast<const float4*>(scale)[j4];
    float4 sh = reinterpret_cast<const float4*>(shift)[j4];
    float4 o;
    o.x = fmaxf(fmaf(v.x, sc.x, sh.x), 0.f);
    o.y = fmaxf(fmaf(v.y, sc.y, sh.y), 0.f);
    o.z = fmaxf(fmaf(v.z, sc.z, sh.z), 0.f);
    o.w = fmaxf(fmaf(v.w, sc.w, sh.w), 0.f);
    reinterpret_cast<float4*>(out)[idx] = o;
}

// ---------------- fused BN + ReLU + classifier (final layer) ----------------
__global__ void bn_cls_kernel(const float* __restrict__ h, const float* __restrict__ scale,
                              const float* __restrict__ shift, const float* __restrict__ Wc,
                              const float* __restrict__ bc, float* __restrict__ out, int n) {
    int warp = (blockIdx.x * blockDim.x + threadIdx.x) >> 5;
    int lane = threadIdx.x & 31;
    if (warp >= n) return;
    float4 v = reinterpret_cast<const float4*>(h + (size_t)warp * 128)[lane];
    float4 sc = reinterpret_cast<const float4*>(scale)[lane];
    float4 sh = reinterpret_cast<const float4*>(shift)[lane];
    int c = lane * 4;
    float w0 = fmaxf(fmaf(v.x, sc.x, sh.x), 0.f);
    float w1 = fmaxf(fmaf(v.y, sc.y, sh.y), 0.f);
    float w2 = fmaxf(fmaf(v.z, sc.z, sh.z), 0.f);
    float w3 = fmaxf(fmaf(v.w, sc.w, sh.w), 0.f);
    float a0 = w0 * Wc[(c + 0) * 2 + 0] + w1 * Wc[(c + 1) * 2 + 0] +
               w2 * Wc[(c + 2) * 2 + 0] + w3 * Wc[(c + 3) * 2 + 0];
    float a1 = w0 * Wc[(c + 0) * 2 + 1] + w1 * Wc[(c + 1) * 2 + 1] +
               w2 * Wc[(c + 2) * 2 + 1] + w3 * Wc[(c + 3) * 2 + 1];
#pragma unroll
    for (int off = 16; off; off >>= 1) {
        a0 += __shfl_xor_sync(0xffffffffu, a0, off);
        a1 += __shfl_xor_sync(0xffffffffu, a1, off);
    }
    if (lane == 0) {
        out[(size_t)warp * 2 + 0] = a0 + bc[0];
        out[(size_t)warp * 2 + 1] = a1 + bc[1];
    }
}

// ---------------- host entry -------------------------------------------------
extern "C" void kernel_launch(void* const* d_in, const int* in_sizes, int n_in,
                              void* d_out, int out_size) {
    const float* x = (const float*)d_in[0];
    const int* src = (const int*)d_in[1];
    const int* dst = (const int*)d_in[2];
    const float* Ws0 = (const float*)d_in[3];
    const float* b0 = (const float*)d_in[4];
    const float* Wn0 = (const float*)d_in[5];
    const float* g0 = (const float*)d_in[6];
    const float* be0 = (const float*)d_in[7];
    const float* Ws1 = (const float*)d_in[8];
    const float* b1 = (const float*)d_in[9];
    const float* Wn1 = (const float*)d_in[10];
    const float* g1 = (const float*)d_in[11];
    const float* be1 = (const float*)d_in[12];
    const float* Ws2 = (const float*)d_in[13];
    const float* b2 = (const float*)d_in[14];
    const float* Wn2 = (const float*)d_in[15];
    const float* g2 = (const float*)d_in[16];
    const float* be2 = (const float*)d_in[17];
    const float* Wc = (const float*)d_in[18];
    const float* bc = (const float*)d_in[19];
    float* out = (float*)d_out;

    int n = in_sizes[0] / 64;
    int E = in_sizes[1];
    float invN = 1.0f / (float)n;

    float *neigh, *h, *xA, *xB, *stats, *scale, *shift;
    __nv_bfloat16 *WtB, *WtS;
    int *cnt, *rowptr, *cursor, *bsum, *eidx;
    cudaGetSymbolAddress((void**)&neigh, g_neigh);
    cudaGetSymbolAddress((void**)&h, g_h);
    cudaGetSymbolAddress((void**)&xA, g_xA);
    cudaGetSymbolAddress((void**)&xB, g_xB);
    cudaGetSymbolAddress((void**)&cnt, g_cnt);
    cudaGetSymbolAddress((void**)&rowptr, g_rowptr);
    cudaGetSymbolAddress((void**)&cursor, g_cursor);
    cudaGetSymbolAddress((void**)&bsum, g_bsum);
    cudaGetSymbolAddress((void**)&eidx, g_eidx);
    cudaGetSymbolAddress((void**)&stats, g_stats);
    cudaGetSymbolAddress((void**)&scale, g_scale);
    cudaGetSymbolAddress((void**)&shift, g_shift);
    cudaGetSymbolAddress((void**)&WtB, g_WtB);
    cudaGetSymbolAddress((void**)&WtS, g_WtS);

    cudaFuncSetAttribute(gemm_wmma_kernel<64>,
                         cudaFuncAttributeMaxDynamicSharedMemorySize, GEMM_SMEM);
    cudaFuncSetAttribute(gemm_wmma_kernel<128>,
                         cudaFuncAttributeMaxDynamicSharedMemorySize, GEMM_SMEM);

    const int T = 256;
    int gb = (n + 127) / 128;
    int nb = (n + 2047) / 2048;
    int gwarp = (n + 7) / 8;

    // ---- CSR build (once, reused by all 3 layers) ----
    zero2_kernel<<<(n / 4 + T - 1) / T, T>>>((float4*)cnt, (float4*)cursor, n / 4);
    zero_kernel<<<1, 64>>>((float4*)stats, 64);   // once; bnparam re-zeros after
    count_kernel<<<(E + T - 1) / T, T>>>(dst, cnt, E);
    scan1_kernel<<<nb, 256>>>(cnt, rowptr, bsum, n);
    scan2_kernel<<<1, 32>>>(bsum, nb);
    scan3_kernel<<<(n + T - 1) / T, T>>>(rowptr, bsum, n);
    fill_kernel<<<(E + T - 1) / T, T>>>(src, dst, rowptr, cursor, eidx, E);

    // ---- layer 0 (DIN = 64) ----
    wsplit_kernel<<<(128 * 128 + T - 1) / T, T>>>(Ws0, Wn0, WtB, WtS, 64);
    gather_kernel<64><<<gwarp, T>>>(x, eidx, rowptr, cnt, neigh, n);
    gemm_wmma_kernel<64><<<gb, T, GEMM_SMEM>>>(x, neigh, WtB, WtS, b0, h, stats, n);
    bnparam_kernel<<<1, 128>>>(stats, g0, be0, scale, shift, invN);
    bn_relu_kernel<<<(n * 32 + T - 1) / T, T>>>(h, scale, shift, xA, n);

    // ---- layer 1 (DIN = 128) ----
    wsplit_kernel<<<(128 * 256 + T - 1) / T, T>>>(Ws1, Wn1, WtB, WtS, 128);
    gather_kernel<128><<<gwarp, T>>>(xA, eidx, rowptr, cnt, neigh, n);
    gemm_wmma_kernel<128><<<gb, T, GEMM_SMEM>>>(xA, neigh, WtB, WtS, b1, h, stats, n);
    bnparam_kernel<<<1, 128>>>(stats, g1, be1, scale, shift, invN);
    bn_relu_kernel<<<(n * 32 + T - 1) / T, T>>>(h, scale, shift, xB, n);

    // ---- layer 2 (DIN = 128) + fused BN/ReLU/classifier ----
    wsplit_kernel<<<(128 * 256 + T - 1) / T, T>>>(Ws2, Wn2, WtB, WtS, 128);
    gather_kernel<128><<<gwarp, T>>>(xB, eidx, rowptr, cnt, neigh, n);
    gemm_wmma_kernel<128><<<gb, T, GEMM_SMEM>>>(xB, neigh, WtB, WtS, b2, h, stats, n);
    bnparam_kernel<<<1, 128>>>(stats, g2, be2, scale, shift, invN);
    bn_cls_kernel<<<(n * 32 + T - 1) / T, T>>>(h, scale, shift, Wc, bc, out, n);
}

// round 15
// speedup vs baseline: 1.2617x; 1.2145x over previous
#include <cuda_runtime.h>
#include <cuda_bf16.h>
#include <mma.h>
#include <cstdint>

using namespace nvcuda;

#define MAXN 100000
#define MAXE 1300000

// ---------------- scratch (static device globals; no allocations allowed) ----
__device__ float g_neigh[MAXN * 128];
__device__ float g_h[MAXN * 128];
__device__ float g_xA[MAXN * 128];
__device__ float g_xB[MAXN * 128];
__device__ int   g_cnt[MAXN];
__device__ int   g_rowptr[MAXN];
__device__ int   g_cursor[MAXN];
__device__ int   g_bsum[128];
__device__ int   g_eidx[MAXE];
__device__ float g_stats[256];   // [0:128) colsum, [128:256) colsumsq
__device__ float g_scale[128];
__device__ float g_shift[128];
__device__ __nv_bfloat16 g_WtB0[128 * 128];  // per-layer pre-split weights
__device__ __nv_bfloat16 g_WtS0[128 * 128];
__device__ __nv_bfloat16 g_WtB1[128 * 256];
__device__ __nv_bfloat16 g_WtS1[128 * 256];
__device__ __nv_bfloat16 g_WtB2[128 * 256];
__device__ __nv_bfloat16 g_WtS2[128 * 256];

// ---------------- utility kernels -------------------------------------------
__global__ void zero_kernel(float4* p, int n4) {
    int i = blockIdx.x * blockDim.x + threadIdx.x;
    if (i < n4) p[i] = make_float4(0.f, 0.f, 0.f, 0.f);
}

__global__ void zero2_kernel(float4* a, float4* b, int n4) {
    int i = blockIdx.x * blockDim.x + threadIdx.x;
    if (i < n4) {
        a[i] = make_float4(0.f, 0.f, 0.f, 0.f);
        b[i] = make_float4(0.f, 0.f, 0.f, 0.f);
    }
}

// ---------------- CSR build --------------------------------------------------
__global__ void count_kernel(const int* __restrict__ dst, int* __restrict__ cnt, int E) {
    int e = blockIdx.x * blockDim.x + threadIdx.x;
    if (e < E) atomicAdd(&cnt[dst[e]], 1);
}

__global__ void scan1_kernel(const int* __restrict__ cnt, int* __restrict__ rowptr,
                             int* __restrict__ bsum, int n) {
    __shared__ int sdata[256];
    int b = blockIdx.x, t = threadIdx.x;
    int base = b * 2048 + t * 8;
    int v[8], s = 0;
#pragma unroll
    for (int i = 0; i < 8; i++) {
        int idx = base + i;
        v[i] = (idx < n) ? cnt[idx] : 0;
        s += v[i];
    }
    sdata[t] = s;
    __syncthreads();
    for (int off = 1; off < 256; off <<= 1) {
        int xv = (t >= off) ? sdata[t - off] : 0;
        __syncthreads();
        sdata[t] += xv;
        __syncthreads();
    }
    int run = sdata[t] - s;
    if (t == 255) bsum[b] = sdata[255];
#pragma unroll
    for (int i = 0; i < 8; i++) {
        int idx = base + i;
        if (idx < n) rowptr[idx] = run;
        run += v[i];
    }
}

__global__ void scan2_kernel(int* __restrict__ bsum, int nb) {
    if (threadIdx.x == 0) {
        int s = 0;
        for (int i = 0; i < nb; i++) { int t = bsum[i]; bsum[i] = s; s += t; }
    }
}

__global__ void scan3_kernel(int* __restrict__ rowptr, const int* __restrict__ bsum, int n) {
    int i = blockIdx.x * blockDim.x + threadIdx.x;
    if (i < n) rowptr[i] += bsum[i >> 11];
}

__global__ void fill_kernel(const int* __restrict__ src, const int* __restrict__ dst,
                            const int* __restrict__ rowptr, int* __restrict__ cursor,
                            int* __restrict__ eidx, int E) {
    int e = blockIdx.x * blockDim.x + threadIdx.x;
    if (e < E) {
        int d = dst[e];
        int p = atomicAdd(&cursor[d], 1);
        eidx[rowptr[d] + p] = src[e];
    }
}

// ---------------- mean aggregation via CSR gather (LEAN — R10 lesson) --------
template <int DIM>
__global__ void gather_kernel(const float* __restrict__ x, const int* __restrict__ eidx,
                              const int* __restrict__ rowptr, const int* __restrict__ cnt,
                              float* __restrict__ neigh, int n) {
    int node = blockIdx.x * (blockDim.x >> 5) + (threadIdx.x >> 5);
    int lane = threadIdx.x & 31;
    if (node >= n) return;
    int start = rowptr[node];
    int d = cnt[node];

    if (DIM == 128) {
        float4 a0 = make_float4(0.f, 0.f, 0.f, 0.f);
        float4 a1 = make_float4(0.f, 0.f, 0.f, 0.f);
        int j = 0;
        for (; j + 4 <= d; j += 4) {
            int s0 = eidx[start + j + 0];
            int s1 = eidx[start + j + 1];
            int s2 = eidx[start + j + 2];
            int s3 = eidx[start + j + 3];
            float4 v0 = *reinterpret_cast<const float4*>(x + (size_t)s0 * 128 + lane * 4);
            float4 v1 = *reinterpret_cast<const float4*>(x + (size_t)s1 * 128 + lane * 4);
            float4 v2 = *reinterpret_cast<const float4*>(x + (size_t)s2 * 128 + lane * 4);
            float4 v3 = *reinterpret_cast<const float4*>(x + (size_t)s3 * 128 + lane * 4);
            a0.x += v0.x + v1.x; a0.y += v0.y + v1.y; a0.z += v0.z + v1.z; a0.w += v0.w + v1.w;
            a1.x += v2.x + v3.x; a1.y += v2.y + v3.y; a1.z += v2.z + v3.z; a1.w += v2.w + v3.w;
        }
        for (; j < d; j++) {
            int s = eidx[start + j];
            float4 v = *reinterpret_cast<const float4*>(x + (size_t)s * 128 + lane * 4);
            a0.x += v.x; a0.y += v.y; a0.z += v.z; a0.w += v.w;
        }
        float inv = 1.0f / (float)max(d, 1);
        float4 o;
        o.x = (a0.x + a1.x) * inv; o.y = (a0.y + a1.y) * inv;
        o.z = (a0.z + a1.z) * inv; o.w = (a0.w + a1.w) * inv;
        *reinterpret_cast<float4*>(neigh + (size_t)node * 128 + lane * 4) = o;
    } else {  // DIM == 64
        float2 a0 = make_float2(0.f, 0.f);
        float2 a1 = make_float2(0.f, 0.f);
        int j = 0;
        for (; j + 4 <= d; j += 4) {
            int s0 = eidx[start + j + 0];
            int s1 = eidx[start + j + 1];
            int s2 = eidx[start + j + 2];
            int s3 = eidx[start + j + 3];
            float2 v0 = *reinterpret_cast<const float2*>(x + (size_t)s0 * 64 + lane * 2);
            float2 v1 = *reinterpret_cast<const float2*>(x + (size_t)s1 * 64 + lane * 2);
            float2 v2 = *reinterpret_cast<const float2*>(x + (size_t)s2 * 64 + lane * 2);
            float2 v3 = *reinterpret_cast<const float2*>(x + (size_t)s3 * 64 + lane * 2);
            a0.x += v0.x + v1.x; a0.y += v0.y + v1.y;
            a1.x += v2.x + v3.x; a1.y += v2.y + v3.y;
        }
        for (; j < d; j++) {
            int s = eidx[start + j];
            float2 v = *reinterpret_cast<const float2*>(x + (size_t)s * 64 + lane * 2);
            a0.x += v.x; a0.y += v.y;
        }
        float inv = 1.0f / (float)max(d, 1);
        float2 o;
        o.x = (a0.x + a1.x) * inv; o.y = (a0.y + a1.y) * inv;
        *reinterpret_cast<float2*>(neigh + (size_t)node * 64 + lane * 2) = o;
    }
}

// ---------------- weight transpose + bf16 big/small split --------------------
__global__ void wsplit_kernel(const float* __restrict__ Ws, const float* __restrict__ Wn,
                              __nv_bfloat16* __restrict__ WtB,
                              __nv_bfloat16* __restrict__ WtS, int DIN) {
    int K = 2 * DIN;
    int idx = blockIdx.x * blockDim.x + threadIdx.x;
    if (idx >= 128 * K) return;
    int nrow = idx / K;
    int k = idx - nrow * K;
    float v = (k < DIN) ? Ws[k * 128 + nrow] : Wn[(k - DIN) * 128 + nrow];
    __nv_bfloat16 b = __float2bfloat16(v);
    float s = v - __bfloat162float(b);
    WtB[idx] = b;
    WtS[idx] = __float2bfloat16(s);
}

// ---------------- wmma bf16 GEMM + BN-stats (3-term split, R7 loop) ----------
// __launch_bounds__(256, 2): cap regs at 128 so 2 CTAs/SM co-reside
// (smem 69120 x 2 = 138 KB < 228 KB). R14 showed reg pressure is the binding
// constraint; this pins occupancy instead of gambling on ptxas.
#define BKP 40                        // padded tile K-stride (bf16 elements)
#define OFF_AS  10240
#define OFF_BB  20480
#define OFF_BS  30720
#define OFF_ST  67584                 // after sD (128 * 132 * 4 = 67584)
#define OFF_ST2 68096
#define OFF_BI  68608
#define GEMM_SMEM 69120

template <int DIN>
__global__ __launch_bounds__(256, 2) void gemm_wmma_kernel(
    const float* __restrict__ x, const float* __restrict__ neigh,
    const __nv_bfloat16* __restrict__ WtB, const __nv_bfloat16* __restrict__ WtS,
    const float* __restrict__ bias, float* __restrict__ h,
    float* __restrict__ stats, int n) {
    constexpr int K = 2 * DIN;
    constexpr int NC = K / 32;

    extern __shared__ char sm[];
    __nv_bfloat16* sAB = (__nv_bfloat16*)(sm);
    __nv_bfloat16* sAS = (__nv_bfloat16*)(sm + OFF_AS);
    __nv_bfloat16* sBB = (__nv_bfloat16*)(sm + OFF_BB);
    __nv_bfloat16* sBS = (__nv_bfloat16*)(sm + OFF_BS);
    float* sD      = (float*)sm;              // [128][132] (epilogue overlay)
    float* sStats  = (float*)(sm + OFF_ST);
    float* sStats2 = (float*)(sm + OFF_ST2);
    float* sBias   = (float*)(sm + OFF_BI);

    int tid = threadIdx.x;
    int row0 = blockIdx.x * 128;
    if (tid < 128) {
        sStats[tid] = 0.f;
        sStats2[tid] = 0.f;
        sBias[tid] = bias[tid];
    }

    int w = tid >> 5;
    int wm = w & 1;    // rows wm*64 .. +63
    int wn = w >> 1;   // cols wn*32 .. +31

    wmma::fragment<wmma::accumulator, 16, 16, 16, float> acc[4][2];
#pragma unroll
    for (int i = 0; i < 4; i++)
#pragma unroll
        for (int j = 0; j < 2; j++) wmma::fill_fragment(acc[i][j], 0.f);

    for (int c = 0; c < NC; c++) {
        bool isSelf = (c * 32 < DIN);
        const float* Asrc = isSelf ? x : neigh;
        int koff = isSelf ? c * 32 : c * 32 - DIN;

        // ---- A tile: 128 rows x 32 f32, split -> bf16 big/small ----
#pragma unroll
        for (int i = 0; i < 4; i++) {
            int f = tid + i * 256;       // 0..1023 quads
            int row = f >> 3;
            int q = f & 7;               // float4 index along k
            int grow = row0 + row;
            float4 v = make_float4(0.f, 0.f, 0.f, 0.f);
            if (grow < n)
                v = *reinterpret_cast<const float4*>(Asrc + (size_t)grow * DIN + koff + q * 4);
            __nv_bfloat16 b0 = __float2bfloat16(v.x), b1 = __float2bfloat16(v.y);
            __nv_bfloat16 b2 = __float2bfloat16(v.z), b3 = __float2bfloat16(v.w);
            __nv_bfloat16 s0 = __float2bfloat16(v.x - __bfloat162float(b0));
            __nv_bfloat16 s1 = __float2bfloat16(v.y - __bfloat162float(b1));
            __nv_bfloat16 s2 = __float2bfloat16(v.z - __bfloat162float(b2));
            __nv_bfloat16 s3 = __float2bfloat16(v.w - __bfloat162float(b3));
            int o = row * BKP + q * 4;
            *reinterpret_cast<__nv_bfloat162*>(sAB + o)     = __nv_bfloat162(b0, b1);
            *reinterpret_cast<__nv_bfloat162*>(sAB + o + 2) = __nv_bfloat162(b2, b3);
            *reinterpret_cast<__nv_bfloat162*>(sAS + o)     = __nv_bfloat162(s0, s1);
            *reinterpret_cast<__nv_bfloat162*>(sAS + o + 2) = __nv_bfloat162(s2, s3);
        }
        // ---- B tile: 128 N-rows x 32 bf16 from pre-split Wt (16B chunks) ----
#pragma unroll
        for (int i = 0; i < 2; i++) {
            int f = tid + i * 256;       // 0..511 oct-groups
            int row = f >> 2;
            int q = f & 3;               // 8-bf16 group along k
            const uint4* pb = reinterpret_cast<const uint4*>(WtB + (size_t)row * K + c * 32 + q * 8);
            const uint4* ps = reinterpret_cast<const uint4*>(WtS + (size_t)row * K + c * 32 + q * 8);
            *reinterpret_cast<uint4*>(sBB + row * BKP + q * 8) = *pb;
            *reinterpret_cast<uint4*>(sBS + row * BKP + q * 8) = *ps;
        }
        __syncthreads();

#pragma unroll
        for (int ks = 0; ks < 2; ks++) {
            int kk = ks * 16;
            wmma::fragment<wmma::matrix_b, 16, 16, 16, __nv_bfloat16, wmma::col_major> fbB[2], fbS[2];
#pragma unroll
            for (int j = 0; j < 2; j++) {
                wmma::load_matrix_sync(fbB[j], sBB + (wn * 32 + j * 16) * BKP + kk, BKP);
                wmma::load_matrix_sync(fbS[j], sBS + (wn * 32 + j * 16) * BKP + kk, BKP);
            }
#pragma unroll
            for (int i = 0; i < 4; i++) {
                wmma::fragment<wmma::matrix_a, 16, 16, 16, __nv_bfloat16, wmma::row_major> faB, faS;
                wmma::load_matrix_sync(faB, sAB + (wm * 64 + i * 16) * BKP + kk, BKP);
                wmma::load_matrix_sync(faS, sAS + (wm * 64 + i * 16) * BKP + kk, BKP);
#pragma unroll
                for (int j = 0; j < 2; j++) {
                    wmma::mma_sync(acc[i][j], faB, fbB[j], acc[i][j]);
                    wmma::mma_sync(acc[i][j], faB, fbS[j], acc[i][j]);
                    wmma::mma_sync(acc[i][j], faS, fbB[j], acc[i][j]);
                }
            }
        }
        __syncthreads();
    }

    // ---- epilogue: fragments -> smem (stride 132), +bias, h stores, stats ----
#pragma unroll
    for (int i = 0; i < 4; i++)
#pragma unroll
        for (int j = 0; j < 2; j++)
            wmma::store_matrix_sync(sD + (wm * 64 + i * 16) * 132 + wn * 32 + j * 16,
                                    acc[i][j], 132, wmma::mem_row_major);
    __syncthreads();
    {
        int cq = tid & 31;   // column quad: cols cq*4 .. +3
        int wr = tid >> 5;   // row stride-8 phase
        float4 bi = *reinterpret_cast<const float4*>(sBias + cq * 4);
        float ps0 = 0.f, ps1 = 0.f, ps2 = 0.f, ps3 = 0.f;
        float pq0 = 0.f, pq1 = 0.f, pq2 = 0.f, pq3 = 0.f;
#pragma unroll
        for (int it = 0; it < 16; it++) {
            int r = wr + it * 8;
            int grow = row0 + r;
            if (grow < n) {
                float v0 = sD[r * 132 + cq * 4 + 0] + bi.x;
                float v1 = sD[r * 132 + cq * 4 + 1] + bi.y;
                float v2 = sD[r * 132 + cq * 4 + 2] + bi.z;
                float v3 = sD[r * 132 + cq * 4 + 3] + bi.w;
                *reinterpret_cast<float4*>(h + (size_t)grow * 128 + cq * 4) =
                    make_float4(v0, v1, v2, v3);
                ps0 += v0; ps1 += v1; ps2 += v2; ps3 += v3;
                pq0 += v0 * v0; pq1 += v1 * v1; pq2 += v2 * v2; pq3 += v3 * v3;
            }
        }
        atomicAdd(&sStats[cq * 4 + 0], ps0); atomicAdd(&sStats2[cq * 4 + 0], pq0);
        atomicAdd(&sStats[cq * 4 + 1], ps1); atomicAdd(&sStats2[cq * 4 + 1], pq1);
        atomicAdd(&sStats[cq * 4 + 2], ps2); atomicAdd(&sStats2[cq * 4 + 2], pq2);
        atomicAdd(&sStats[cq * 4 + 3], ps3); atomicAdd(&sStats2[cq * 4 + 3], pq3);
    }
    __syncthreads();
    if (tid < 128) {
        atomicAdd(&stats[tid], sStats[tid]);
        atomicAdd(&stats[128 + tid], sStats2[tid]);
    }
}

// ---------------- BN parameter folding (also resets stats for next layer) ----
__global__ void bnparam_kernel(float* __restrict__ stats, const float* __restrict__ gamma,
                               const float* __restrict__ beta, float* __restrict__ scale,
                               float* __restrict__ shift, float invN) {
    int j = threadIdx.x;
    float mu = stats[j] * invN;
    float var = stats[128 + j] * invN - mu * mu;
    float sc = gamma[j] * rsqrtf(var + 1e-5f);
    scale[j] = sc;
    shift[j] = fmaf(-mu, sc, beta[j]);
    stats[j] = 0.f;
    stats[128 + j] = 0.f;
}

// ---------------- BN apply + ReLU (elementwise, float4) ---------------------
__global__ void bn_relu_kernel(const float* __restrict__ h, const float* __restrict__ scale,
                               const float* __restrict__ shift, float* __restrict__ out, int n) {
    int idx = blockIdx.x * blockDim.x + threadIdx.x;
    if (idx >= n * 32) return;
    int j4 = idx & 31;
    float4 v = reinterpret_cast<const float4*>(h)[idx];
    float4 sc = reinterpret_cast<const float4*>(scale)[j4];
    float4 sh = reinterpret_cast<const float4*>(shift)[j4];
    float4 o;
    o.x = fmaxf(fmaf(v.x, sc.x, sh.x), 0.f);
    o.y = fmaxf(fmaf(v.y, sc.y, sh.y), 0.f);
    o.z = fmaxf(fmaf(v.z, sc.z, sh.z), 0.f);
    o.w = fmaxf(fmaf(v.w, sc.w, sh.w), 0.f);
    reinterpret_cast<float4*>(out)[idx] = o;
}

// ---------------- fused BN + ReLU + classifier (final layer) ----------------
__global__ void bn_cls_kernel(const float* __restrict__ h, const float* __restrict__ scale,
                              const float* __restrict__ shift, const float* __restrict__ Wc,
                              const float* __restrict__ bc, float* __restrict__ out, int n) {
    int warp = (blockIdx.x * blockDim.x + threadIdx.x) >> 5;
    int lane = threadIdx.x & 31;
    if (warp >= n) return;
    float4 v = reinterpret_cast<const float4*>(h + (size_t)warp * 128)[lane];
    float4 sc = reinterpret_cast<const float4*>(scale)[lane];
    float4 sh = reinterpret_cast<const float4*>(shift)[lane];
    int c = lane * 4;
    float w0 = fmaxf(fmaf(v.x, sc.x, sh.x), 0.f);
    float w1 = fmaxf(fmaf(v.y, sc.y, sh.y), 0.f);
    float w2 = fmaxf(fmaf(v.z, sc.z, sh.z), 0.f);
    float w3 = fmaxf(fmaf(v.w, sc.w, sh.w), 0.f);
    float a0 = w0 * Wc[(c + 0) * 2 + 0] + w1 * Wc[(c + 1) * 2 + 0] +
               w2 * Wc[(c + 2) * 2 + 0] + w3 * Wc[(c + 3) * 2 + 0];
    float a1 = w0 * Wc[(c + 0) * 2 + 1] + w1 * Wc[(c + 1) * 2 + 1] +
               w2 * Wc[(c + 2) * 2 + 1] + w3 * Wc[(c + 3) * 2 + 1];
#pragma unroll
    for (int off = 16; off; off >>= 1) {
        a0 += __shfl_xor_sync(0xffffffffu, a0, off);
        a1 += __shfl_xor_sync(0xffffffffu, a1, off);
    }
    if (lane == 0) {
        out[(size_t)warp * 2 + 0] = a0 + bc[0];
        out[(size_t)warp * 2 + 1] = a1 + bc[1];
    }
}

// ---------------- host entry -------------------------------------------------
extern "C" void kernel_launch(void* const* d_in, const int* in_sizes, int n_in,
                              void* d_out, int out_size) {
    const float* x = (const float*)d_in[0];
    const int* src = (const int*)d_in[1];
    const int* dst = (const int*)d_in[2];
    const float* Ws0 = (const float*)d_in[3];
    const float* b0 = (const float*)d_in[4];
    const float* Wn0 = (const float*)d_in[5];
    const float* g0 = (const float*)d_in[6];
    const float* be0 = (const float*)d_in[7];
    const float* Ws1 = (const float*)d_in[8];
    const float* b1 = (const float*)d_in[9];
    const float* Wn1 = (const float*)d_in[10];
    const float* g1 = (const float*)d_in[11];
    const float* be1 = (const float*)d_in[12];
    const float* Ws2 = (const float*)d_in[13];
    const float* b2 = (const float*)d_in[14];
    const float* Wn2 = (const float*)d_in[15];
    const float* g2 = (const float*)d_in[16];
    const float* be2 = (const float*)d_in[17];
    const float* Wc = (const float*)d_in[18];
    const float* bc = (const float*)d_in[19];
    float* out = (float*)d_out;

    int n = in_sizes[0] / 64;
    int E = in_sizes[1];
    float invN = 1.0f / (float)n;

    float *neigh, *h, *xA, *xB, *stats, *scale, *shift;
    __nv_bfloat16 *WtB0, *WtS0, *WtB1, *WtS1, *WtB2, *WtS2;
    int *cnt, *rowptr, *cursor, *bsum, *eidx;
    cudaGetSymbolAddress((void**)&neigh, g_neigh);
    cudaGetSymbolAddress((void**)&h, g_h);
    cudaGetSymbolAddress((void**)&xA, g_xA);
    cudaGetSymbolAddress((void**)&xB, g_xB);
    cudaGetSymbolAddress((void**)&cnt, g_cnt);
    cudaGetSymbolAddress((void**)&rowptr, g_rowptr);
    cudaGetSymbolAddress((void**)&cursor, g_cursor);
    cudaGetSymbolAddress((void**)&bsum, g_bsum);
    cudaGetSymbolAddress((void**)&eidx, g_eidx);
    cudaGetSymbolAddress((void**)&stats, g_stats);
    cudaGetSymbolAddress((void**)&scale, g_scale);
    cudaGetSymbolAddress((void**)&shift, g_shift);
    cudaGetSymbolAddress((void**)&WtB0, g_WtB0);
    cudaGetSymbolAddress((void**)&WtS0, g_WtS0);
    cudaGetSymbolAddress((void**)&WtB1, g_WtB1);
    cudaGetSymbolAddress((void**)&WtS1, g_WtS1);
    cudaGetSymbolAddress((void**)&WtB2, g_WtB2);
    cudaGetSymbolAddress((void**)&WtS2, g_WtS2);

    cudaFuncSetAttribute(gemm_wmma_kernel<64>,
                         cudaFuncAttributeMaxDynamicSharedMemorySize, GEMM_SMEM);
    cudaFuncSetAttribute(gemm_wmma_kernel<128>,
                         cudaFuncAttributeMaxDynamicSharedMemorySize, GEMM_SMEM);

    const int T = 256;
    int gb = (n + 127) / 128;
    int nb = (n + 2047) / 2048;
    int gwarp = (n + 7) / 8;

    // ---- all weight splits up front (off the inter-layer critical path) ----
    wsplit_kernel<<<(128 * 128 + T - 1) / T, T>>>(Ws0, Wn0, WtB0, WtS0, 64);
    wsplit_kernel<<<(128 * 256 + T - 1) / T, T>>>(Ws1, Wn1, WtB1, WtS1, 128);
    wsplit_kernel<<<(128 * 256 + T - 1) / T, T>>>(Ws2, Wn2, WtB2, WtS2, 128);

    // ---- CSR build (once, reused by all 3 layers) ----
    zero2_kernel<<<(n / 4 + T - 1) / T, T>>>((float4*)cnt, (float4*)cursor, n / 4);
    zero_kernel<<<1, 64>>>((float4*)stats, 64);   // once; bnparam re-zeros after
    count_kernel<<<(E + T - 1) / T, T>>>(dst, cnt, E);
    scan1_kernel<<<nb, 256>>>(cnt, rowptr, bsum, n);
    scan2_kernel<<<1, 32>>>(bsum, nb);
    scan3_kernel<<<(n + T - 1) / T, T>>>(rowptr, bsum, n);
    fill_kernel<<<(E + T - 1) / T, T>>>(src, dst, rowptr, cursor, eidx, E);

    // ---- layer 0 (DIN = 64) ----
    gather_kernel<64><<<gwarp, T>>>(x, eidx, rowptr, cnt, neigh, n);
    gemm_wmma_kernel<64><<<gb, T, GEMM_SMEM>>>(x, neigh, WtB0, WtS0, b0, h, stats, n);
    bnparam_kernel<<<1, 128>>>(stats, g0, be0, scale, shift, invN);
    bn_relu_kernel<<<(n * 32 + T - 1) / T, T>>>(h, scale, shift, xA, n);

    // ---- layer 1 (DIN = 128) ----
    gather_kernel<128><<<gwarp, T>>>(xA, eidx, rowptr, cnt, neigh, n);
    gemm_wmma_kernel<128><<<gb, T, GEMM_SMEM>>>(xA, neigh, WtB1, WtS1, b1, h, stats, n);
    bnparam_kernel<<<1, 128>>>(stats, g1, be1, scale, shift, invN);
    bn_relu_kernel<<<(n * 32 + T - 1) / T, T>>>(h, scale, shift, xB, n);

    // ---- layer 2 (DIN = 128) + fused BN/ReLU/classifier ----
    gather_kernel<128><<<gwarp, T>>>(xB, eidx, rowptr, cnt, neigh, n);
    gemm_wmma_kernel<128><<<gb, T, GEMM_SMEM>>>(xB, neigh, WtB2, WtS2, b2, h, stats, n);
    bnparam_kernel<<<1, 128>>>(stats, g2, be2, scale, shift, invN);
    bn_cls_kernel<<<(n * 32 + T - 1) / T, T>>>(h, scale, shift, Wc, bc, out, n);
}

// round 16
// speedup vs baseline: 1.2912x; 1.0234x over previous
#include <cuda_runtime.h>
#include <cuda_bf16.h>
#include <cuda_fp16.h>
#include <mma.h>
#include <cstdint>

using namespace nvcuda;

#define MAXN 100000
#define MAXE 1300000

// ---------------- scratch (static device globals; no allocations allowed) ----
__device__ float g_neigh[MAXN * 128];
__device__ float g_h[MAXN * 128];
__device__ float g_xA[MAXN * 128];
__device__ float g_xB[MAXN * 128];
__device__ __half g_xh[MAXN * 128];   // fp16 shadow of activations (gather reads)
__device__ int   g_cnt[MAXN];
__device__ int   g_rowptr[MAXN];
__device__ int   g_cursor[MAXN];
__device__ int   g_bsum[128];
__device__ int   g_eidx[MAXE];
__device__ float g_stats[256];   // [0:128) colsum, [128:256) colsumsq
__device__ float g_scale[128];
__device__ float g_shift[128];
__device__ __nv_bfloat16 g_WtB0[128 * 128];  // per-layer pre-split weights
__device__ __nv_bfloat16 g_WtS0[128 * 128];
__device__ __nv_bfloat16 g_WtB1[128 * 256];
__device__ __nv_bfloat16 g_WtS1[128 * 256];
__device__ __nv_bfloat16 g_WtB2[128 * 256];
__device__ __nv_bfloat16 g_WtS2[128 * 256];

// ---------------- utility kernels -------------------------------------------
__global__ void zero_kernel(float4* p, int n4) {
    int i = blockIdx.x * blockDim.x + threadIdx.x;
    if (i < n4) p[i] = make_float4(0.f, 0.f, 0.f, 0.f);
}

__global__ void zero2_kernel(float4* a, float4* b, int n4) {
    int i = blockIdx.x * blockDim.x + threadIdx.x;
    if (i < n4) {
        a[i] = make_float4(0.f, 0.f, 0.f, 0.f);
        b[i] = make_float4(0.f, 0.f, 0.f, 0.f);
    }
}

// fp32 -> fp16 convert (layer-0 input shadow)
__global__ void xcvt_kernel(const float4* __restrict__ x, uint2* __restrict__ xh, int n4) {
    int i = blockIdx.x * blockDim.x + threadIdx.x;
    if (i >= n4) return;
    float4 v = x[i];
    __half2 h0 = __floats2half2_rn(v.x, v.y);
    __half2 h1 = __floats2half2_rn(v.z, v.w);
    uint2 o;
    o.x = *reinterpret_cast<uint32_t*>(&h0);
    o.y = *reinterpret_cast<uint32_t*>(&h1);
    xh[i] = o;
}

// ---------------- CSR build --------------------------------------------------
__global__ void count_kernel(const int* __restrict__ dst, int* __restrict__ cnt, int E) {
    int e = blockIdx.x * blockDim.x + threadIdx.x;
    if (e < E) atomicAdd(&cnt[dst[e]], 1);
}

__global__ void scan1_kernel(const int* __restrict__ cnt, int* __restrict__ rowptr,
                             int* __restrict__ bsum, int n) {
    __shared__ int sdata[256];
    int b = blockIdx.x, t = threadIdx.x;
    int base = b * 2048 + t * 8;
    int v[8], s = 0;
#pragma unroll
    for (int i = 0; i < 8; i++) {
        int idx = base + i;
        v[i] = (idx < n) ? cnt[idx] : 0;
        s += v[i];
    }
    sdata[t] = s;
    __syncthreads();
    for (int off = 1; off < 256; off <<= 1) {
        int xv = (t >= off) ? sdata[t - off] : 0;
        __syncthreads();
        sdata[t] += xv;
        __syncthreads();
    }
    int run = sdata[t] - s;
    if (t == 255) bsum[b] = sdata[255];
#pragma unroll
    for (int i = 0; i < 8; i++) {
        int idx = base + i;
        if (idx < n) rowptr[idx] = run;
        run += v[i];
    }
}

__global__ void scan2_kernel(int* __restrict__ bsum, int nb) {
    if (threadIdx.x == 0) {
        int s = 0;
        for (int i = 0; i < nb; i++) { int t = bsum[i]; bsum[i] = s; s += t; }
    }
}

__global__ void scan3_kernel(int* __restrict__ rowptr, const int* __restrict__ bsum, int n) {
    int i = blockIdx.x * blockDim.x + threadIdx.x;
    if (i < n) rowptr[i] += bsum[i >> 11];
}

__global__ void fill_kernel(const int* __restrict__ src, const int* __restrict__ dst,
                            const int* __restrict__ rowptr, int* __restrict__ cursor,
                            int* __restrict__ eidx, int E) {
    int e = blockIdx.x * blockDim.x + threadIdx.x;
    if (e < E) {
        int d = dst[e];
        int p = atomicAdd(&cursor[d], 1);
        eidx[rowptr[d] + p] = src[e];
    }
}

// ---------------- mean aggregation via CSR gather (fp16 reads, fp32 accum) ---
// One warp per node. Reads the fp16 shadow (half the L2 traffic of fp32);
// converts in-register (2 cvt per row segment — gather is bandwidth-bound).
template <int DIM>
__global__ void gather_kernel(const __half* __restrict__ xh, const int* __restrict__ eidx,
                              const int* __restrict__ rowptr, const int* __restrict__ cnt,
                              float* __restrict__ neigh, int n) {
    int node = blockIdx.x * (blockDim.x >> 5) + (threadIdx.x >> 5);
    int lane = threadIdx.x & 31;
    if (node >= n) return;
    int start = rowptr[node];
    int d = cnt[node];

    if (DIM == 128) {
        float4 a0 = make_float4(0.f, 0.f, 0.f, 0.f);
        float4 a1 = make_float4(0.f, 0.f, 0.f, 0.f);
        int j = 0;
        for (; j + 4 <= d; j += 4) {
            int s0 = eidx[start + j + 0];
            int s1 = eidx[start + j + 1];
            int s2 = eidx[start + j + 2];
            int s3 = eidx[start + j + 3];
            uint2 r0 = *reinterpret_cast<const uint2*>(xh + (size_t)s0 * 128 + lane * 4);
            uint2 r1 = *reinterpret_cast<const uint2*>(xh + (size_t)s1 * 128 + lane * 4);
            uint2 r2 = *reinterpret_cast<const uint2*>(xh + (size_t)s2 * 128 + lane * 4);
            uint2 r3 = *reinterpret_cast<const uint2*>(xh + (size_t)s3 * 128 + lane * 4);
            float2 f0a = __half22float2(*reinterpret_cast<__half2*>(&r0.x));
            float2 f0b = __half22float2(*reinterpret_cast<__half2*>(&r0.y));
            float2 f1a = __half22float2(*reinterpret_cast<__half2*>(&r1.x));
            float2 f1b = __half22float2(*reinterpret_cast<__half2*>(&r1.y));
            float2 f2a = __half22float2(*reinterpret_cast<__half2*>(&r2.x));
            float2 f2b = __half22float2(*reinterpret_cast<__half2*>(&r2.y));
            float2 f3a = __half22float2(*reinterpret_cast<__half2*>(&r3.x));
            float2 f3b = __half22float2(*reinterpret_cast<__half2*>(&r3.y));
            a0.x += f0a.x + f1a.x; a0.y += f0a.y + f1a.y;
            a0.z += f0b.x + f1b.x; a0.w += f0b.y + f1b.y;
            a1.x += f2a.x + f3a.x; a1.y += f2a.y + f3a.y;
            a1.z += f2b.x + f3b.x; a1.w += f2b.y + f3b.y;
        }
        for (; j < d; j++) {
            int s = eidx[start + j];
            uint2 r = *reinterpret_cast<const uint2*>(xh + (size_t)s * 128 + lane * 4);
            float2 fa = __half22float2(*reinterpret_cast<__half2*>(&r.x));
            float2 fb = __half22float2(*reinterpret_cast<__half2*>(&r.y));
            a0.x += fa.x; a0.y += fa.y; a0.z += fb.x; a0.w += fb.y;
        }
        float inv = 1.0f / (float)max(d, 1);
        float4 o;
        o.x = (a0.x + a1.x) * inv; o.y = (a0.y + a1.y) * inv;
        o.z = (a0.z + a1.z) * inv; o.w = (a0.w + a1.w) * inv;
        *reinterpret_cast<float4*>(neigh + (size_t)node * 128 + lane * 4) = o;
    } else {  // DIM == 64
        float2 a0 = make_float2(0.f, 0.f);
        float2 a1 = make_float2(0.f, 0.f);
        int j = 0;
        for (; j + 4 <= d; j += 4) {
            int s0 = eidx[start + j + 0];
            int s1 = eidx[start + j + 1];
            int s2 = eidx[start + j + 2];
            int s3 = eidx[start + j + 3];
            uint32_t r0 = *reinterpret_cast<const uint32_t*>(xh + (size_t)s0 * 64 + lane * 2);
            uint32_t r1 = *reinterpret_cast<const uint32_t*>(xh + (size_t)s1 * 64 + lane * 2);
            uint32_t r2 = *reinterpret_cast<const uint32_t*>(xh + (size_t)s2 * 64 + lane * 2);
            uint32_t r3 = *reinterpret_cast<const uint32_t*>(xh + (size_t)s3 * 64 + lane * 2);
            float2 f0 = __half22float2(*reinterpret_cast<__half2*>(&r0));
            float2 f1 = __half22float2(*reinterpret_cast<__half2*>(&r1));
            float2 f2 = __half22float2(*reinterpret_cast<__half2*>(&r2));
            float2 f3 = __half22float2(*reinterpret_cast<__half2*>(&r3));
            a0.x += f0.x + f1.x; a0.y += f0.y + f1.y;
            a1.x += f2.x + f3.x; a1.y += f2.y + f3.y;
        }
        for (; j < d; j++) {
            int s = eidx[start + j];
            uint32_t r = *reinterpret_cast<const uint32_t*>(xh + (size_t)s * 64 + lane * 2);
            float2 f = __half22float2(*reinterpret_cast<__half2*>(&r));
            a0.x += f.x; a0.y += f.y;
        }
        float inv = 1.0f / (float)max(d, 1);
        float2 o;
        o.x = (a0.x + a1.x) * inv; o.y = (a0.y + a1.y) * inv;
        *reinterpret_cast<float2*>(neigh + (size_t)node * 64 + lane * 2) = o;
    }
}

// ---------------- weight transpose + bf16 big/small split --------------------
__global__ void wsplit_kernel(const float* __restrict__ Ws, const float* __restrict__ Wn,
                              __nv_bfloat16* __restrict__ WtB,
                              __nv_bfloat16* __restrict__ WtS, int DIN) {
    int K = 2 * DIN;
    int idx = blockIdx.x * blockDim.x + threadIdx.x;
    if (idx >= 128 * K) return;
    int nrow = idx / K;
    int k = idx - nrow * K;
    float v = (k < DIN) ? Ws[k * 128 + nrow] : Wn[(k - DIN) * 128 + nrow];
    __nv_bfloat16 b = __float2bfloat16(v);
    float s = v - __bfloat162float(b);
    WtB[idx] = b;
    WtS[idx] = __float2bfloat16(s);
}

// ---------------- wmma bf16 GEMM + BN-stats (3-term split, R15 winner) -------
#define BKP 40                        // padded tile K-stride (bf16 elements)
#define OFF_AS  10240
#define OFF_BB  20480
#define OFF_BS  30720
#define OFF_ST  67584                 // after sD (128 * 132 * 4 = 67584)
#define OFF_ST2 68096
#define OFF_BI  68608
#define GEMM_SMEM 69120

template <int DIN>
__global__ __launch_bounds__(256, 2) void gemm_wmma_kernel(
    const float* __restrict__ x, const float* __restrict__ neigh,
    const __nv_bfloat16* __restrict__ WtB, const __nv_bfloat16* __restrict__ WtS,
    const float* __restrict__ bias, float* __restrict__ h,
    float* __restrict__ stats, int n) {
    constexpr int K = 2 * DIN;
    constexpr int NC = K / 32;

    extern __shared__ char sm[];
    __nv_bfloat16* sAB = (__nv_bfloat16*)(sm);
    __nv_bfloat16* sAS = (__nv_bfloat16*)(sm + OFF_AS);
    __nv_bfloat16* sBB = (__nv_bfloat16*)(sm + OFF_BB);
    __nv_bfloat16* sBS = (__nv_bfloat16*)(sm + OFF_BS);
    float* sD      = (float*)sm;              // [128][132] (epilogue overlay)
    float* sStats  = (float*)(sm + OFF_ST);
    float* sStats2 = (float*)(sm + OFF_ST2);
    float* sBias   = (float*)(sm + OFF_BI);

    int tid = threadIdx.x;
    int row0 = blockIdx.x * 128;
    if (tid < 128) {
        sStats[tid] = 0.f;
        sStats2[tid] = 0.f;
        sBias[tid] = bias[tid];
    }

    int w = tid >> 5;
    int wm = w & 1;    // rows wm*64 .. +63
    int wn = w >> 1;   // cols wn*32 .. +31

    wmma::fragment<wmma::accumulator, 16, 16, 16, float> acc[4][2];
#pragma unroll
    for (int i = 0; i < 4; i++)
#pragma unroll
        for (int j = 0; j < 2; j++) wmma::fill_fragment(acc[i][j], 0.f);

    for (int c = 0; c < NC; c++) {
        bool isSelf = (c * 32 < DIN);
        const float* Asrc = isSelf ? x : neigh;
        int koff = isSelf ? c * 32 : c * 32 - DIN;

        // ---- A tile: 128 rows x 32 f32, split -> bf16 big/small ----
#pragma unroll
        for (int i = 0; i < 4; i++) {
            int f = tid + i * 256;       // 0..1023 quads
            int row = f >> 3;
            int q = f & 7;               // float4 index along k
            int grow = row0 + row;
            float4 v = make_float4(0.f, 0.f, 0.f, 0.f);
            if (grow < n)
                v = *reinterpret_cast<const float4*>(Asrc + (size_t)grow * DIN + koff + q * 4);
            __nv_bfloat16 b0 = __float2bfloat16(v.x), b1 = __float2bfloat16(v.y);
            __nv_bfloat16 b2 = __float2bfloat16(v.z), b3 = __float2bfloat16(v.w);
            __nv_bfloat16 s0 = __float2bfloat16(v.x - __bfloat162float(b0));
            __nv_bfloat16 s1 = __float2bfloat16(v.y - __bfloat162float(b1));
            __nv_bfloat16 s2 = __float2bfloat16(v.z - __bfloat162float(b2));
            __nv_bfloat16 s3 = __float2bfloat16(v.w - __bfloat162float(b3));
            int o = row * BKP + q * 4;
            *reinterpret_cast<__nv_bfloat162*>(sAB + o)     = __nv_bfloat162(b0, b1);
            *reinterpret_cast<__nv_bfloat162*>(sAB + o + 2) = __nv_bfloat162(b2, b3);
            *reinterpret_cast<__nv_bfloat162*>(sAS + o)     = __nv_bfloat162(s0, s1);
            *reinterpret_cast<__nv_bfloat162*>(sAS + o + 2) = __nv_bfloat162(s2, s3);
        }
        // ---- B tile: 128 N-rows x 32 bf16 from pre-split Wt (16B chunks) ----
#pragma unroll
        for (int i = 0; i < 2; i++) {
            int f = tid + i * 256;       // 0..511 oct-groups
            int row = f >> 2;
            int q = f & 3;               // 8-bf16 group along k
            const uint4* pb = reinterpret_cast<const uint4*>(WtB + (size_t)row * K + c * 32 + q * 8);
            const uint4* ps = reinterpret_cast<const uint4*>(WtS + (size_t)row * K + c * 32 + q * 8);
            *reinterpret_cast<uint4*>(sBB + row * BKP + q * 8) = *pb;
            *reinterpret_cast<uint4*>(sBS + row * BKP + q * 8) = *ps;
        }
        __syncthreads();

#pragma unroll
        for (int ks = 0; ks < 2; ks++) {
            int kk = ks * 16;
            wmma::fragment<wmma::matrix_b, 16, 16, 16, __nv_bfloat16, wmma::col_major> fbB[2], fbS[2];
#pragma unroll
            for (int j = 0; j < 2; j++) {
                wmma::load_matrix_sync(fbB[j], sBB + (wn * 32 + j * 16) * BKP + kk, BKP);
                wmma::load_matrix_sync(fbS[j], sBS + (wn * 32 + j * 16) * BKP + kk, BKP);
            }
#pragma unroll
            for (int i = 0; i < 4; i++) {
                wmma::fragment<wmma::matrix_a, 16, 16, 16, __nv_bfloat16, wmma::row_major> faB, faS;
                wmma::load_matrix_sync(faB, sAB + (wm * 64 + i * 16) * BKP + kk, BKP);
                wmma::load_matrix_sync(faS, sAS + (wm * 64 + i * 16) * BKP + kk, BKP);
#pragma unroll
                for (int j = 0; j < 2; j++) {
                    wmma::mma_sync(acc[i][j], faB, fbB[j], acc[i][j]);
                    wmma::mma_sync(acc[i][j], faB, fbS[j], acc[i][j]);
                    wmma::mma_sync(acc[i][j], faS, fbB[j], acc[i][j]);
                }
            }
        }
        __syncthreads();
    }

    // ---- epilogue: fragments -> smem (stride 132), +bias, h stores, stats ----
#pragma unroll
    for (int i = 0; i < 4; i++)
#pragma unroll
        for (int j = 0; j < 2; j++)
            wmma::store_matrix_sync(sD + (wm * 64 + i * 16) * 132 + wn * 32 + j * 16,
                                    acc[i][j], 132, wmma::mem_row_major);
    __syncthreads();
    {
        int cq = tid & 31;   // column quad: cols cq*4 .. +3
        int wr = tid >> 5;   // row stride-8 phase
        float4 bi = *reinterpret_cast<const float4*>(sBias + cq * 4);
        float ps0 = 0.f, ps1 = 0.f, ps2 = 0.f, ps3 = 0.f;
        float pq0 = 0.f, pq1 = 0.f, pq2 = 0.f, pq3 = 0.f;
#pragma unroll
        for (int it = 0; it < 16; it++) {
            int r = wr + it * 8;
            int grow = row0 + r;
            if (grow < n) {
                float v0 = sD[r * 132 + cq * 4 + 0] + bi.x;
                float v1 = sD[r * 132 + cq * 4 + 1] + bi.y;
                float v2 = sD[r * 132 + cq * 4 + 2] + bi.z;
                float v3 = sD[r * 132 + cq * 4 + 3] + bi.w;
                *reinterpret_cast<float4*>(h + (size_t)grow * 128 + cq * 4) =
                    make_float4(v0, v1, v2, v3);
                ps0 += v0; ps1 += v1; ps2 += v2; ps3 += v3;
                pq0 += v0 * v0; pq1 += v1 * v1; pq2 += v2 * v2; pq3 += v3 * v3;
            }
        }
        atomicAdd(&sStats[cq * 4 + 0], ps0); atomicAdd(&sStats2[cq * 4 + 0], pq0);
        atomicAdd(&sStats[cq * 4 + 1], ps1); atomicAdd(&sStats2[cq * 4 + 1], pq1);
        atomicAdd(&sStats[cq * 4 + 2], ps2); atomicAdd(&sStats2[cq * 4 + 2], pq2);
        atomicAdd(&sStats[cq * 4 + 3], ps3); atomicAdd(&sStats2[cq * 4 + 3], pq3);
    }
    __syncthreads();
    if (tid < 128) {
        atomicAdd(&stats[tid], sStats[tid]);
        atomicAdd(&stats[128 + tid], sStats2[tid]);
    }
}

// ---------------- BN parameter folding (also resets stats for next layer) ----
__global__ void bnparam_kernel(float* __restrict__ stats, const float* __restrict__ gamma,
                               const float* __restrict__ beta, float* __restrict__ scale,
                               float* __restrict__ shift, float invN) {
    int j = threadIdx.x;
    float mu = stats[j] * invN;
    float var = stats[128 + j] * invN - mu * mu;
    float sc = gamma[j] * rsqrtf(var + 1e-5f);
    scale[j] = sc;
    shift[j] = fmaf(-mu, sc, beta[j]);
    stats[j] = 0.f;
    stats[128 + j] = 0.f;
}

// ---------------- BN apply + ReLU (fp32 out + fp16 shadow out) ---------------
__global__ void bn_relu_kernel(const float* __restrict__ h, const float* __restrict__ scale,
                               const float* __restrict__ shift, float* __restrict__ out,
                               uint2* __restrict__ outh, int n) {
    int idx = blockIdx.x * blockDim.x + threadIdx.x;
    if (idx >= n * 32) return;
    int j4 = idx & 31;
    float4 v = reinterpret_cast<const float4*>(h)[idx];
    float4 sc = reinterpret_cast<const float4*>(scale)[j4];
    float4 sh = reinterpret_cast<const float4*>(shift)[j4];
    float4 o;
    o.x = fmaxf(fmaf(v.x, sc.x, sh.x), 0.f);
    o.y = fmaxf(fmaf(v.y, sc.y, sh.y), 0.f);
    o.z = fmaxf(fmaf(v.z, sc.z, sh.z), 0.f);
    o.w = fmaxf(fmaf(v.w, sc.w, sh.w), 0.f);
    reinterpret_cast<float4*>(out)[idx] = o;
    __half2 h0 = __floats2half2_rn(o.x, o.y);
    __half2 h1 = __floats2half2_rn(o.z, o.w);
    uint2 oh;
    oh.x = *reinterpret_cast<uint32_t*>(&h0);
    oh.y = *reinterpret_cast<uint32_t*>(&h1);
    outh[idx] = oh;
}

// ---------------- fused BN + ReLU + classifier (final layer) ----------------
__global__ void bn_cls_kernel(const float* __restrict__ h, const float* __restrict__ scale,
                              const float* __restrict__ shift, const float* __restrict__ Wc,
                              const float* __restrict__ bc, float* __restrict__ out, int n) {
    int warp = (blockIdx.x * blockDim.x + threadIdx.x) >> 5;
    int lane = threadIdx.x & 31;
    if (warp >= n) return;
    float4 v = reinterpret_cast<const float4*>(h + (size_t)warp * 128)[lane];
    float4 sc = reinterpret_cast<const float4*>(scale)[lane];
    float4 sh = reinterpret_cast<const float4*>(shift)[lane];
    int c = lane * 4;
    float w0 = fmaxf(fmaf(v.x, sc.x, sh.x), 0.f);
    float w1 = fmaxf(fmaf(v.y, sc.y, sh.y), 0.f);
    float w2 = fmaxf(fmaf(v.z, sc.z, sh.z), 0.f);
    float w3 = fmaxf(fmaf(v.w, sc.w, sh.w), 0.f);
    float a0 = w0 * Wc[(c + 0) * 2 + 0] + w1 * Wc[(c + 1) * 2 + 0] +
               w2 * Wc[(c + 2) * 2 + 0] + w3 * Wc[(c + 3) * 2 + 0];
    float a1 = w0 * Wc[(c + 0) * 2 + 1] + w1 * Wc[(c + 1) * 2 + 1] +
               w2 * Wc[(c + 2) * 2 + 1] + w3 * Wc[(c + 3) * 2 + 1];
#pragma unroll
    for (int off = 16; off; off >>= 1) {
        a0 += __shfl_xor_sync(0xffffffffu, a0, off);
        a1 += __shfl_xor_sync(0xffffffffu, a1, off);
    }
    if (lane == 0) {
        out[(size_t)warp * 2 + 0] = a0 + bc[0];
        out[(size_t)warp * 2 + 1] = a1 + bc[1];
    }
}

// ---------------- host entry -------------------------------------------------
extern "C" void kernel_launch(void* const* d_in, const int* in_sizes, int n_in,
                              void* d_out, int out_size) {
    const float* x = (const float*)d_in[0];
    const int* src = (const int*)d_in[1];
    const int* dst = (const int*)d_in[2];
    const float* Ws0 = (const float*)d_in[3];
    const float* b0 = (const float*)d_in[4];
    const float* Wn0 = (const float*)d_in[5];
    const float* g0 = (const float*)d_in[6];
    const float* be0 = (const float*)d_in[7];
    const float* Ws1 = (const float*)d_in[8];
    const float* b1 = (const float*)d_in[9];
    const float* Wn1 = (const float*)d_in[10];
    const float* g1 = (const float*)d_in[11];
    const float* be1 = (const float*)d_in[12];
    const float* Ws2 = (const float*)d_in[13];
    const float* b2 = (const float*)d_in[14];
    const float* Wn2 = (const float*)d_in[15];
    const float* g2 = (const float*)d_in[16];
    const float* be2 = (const float*)d_in[17];
    const float* Wc = (const float*)d_in[18];
    const float* bc = (const float*)d_in[19];
    float* out = (float*)d_out;

    int n = in_sizes[0] / 64;
    int E = in_sizes[1];
    float invN = 1.0f / (float)n;

    float *neigh, *h, *xA, *xB, *stats, *scale, *shift;
    __half* xh;
    __nv_bfloat16 *WtB0, *WtS0, *WtB1, *WtS1, *WtB2, *WtS2;
    int *cnt, *rowptr, *cursor, *bsum, *eidx;
    cudaGetSymbolAddress((void**)&neigh, g_neigh);
    cudaGetSymbolAddress((void**)&h, g_h);
    cudaGetSymbolAddress((void**)&xA, g_xA);
    cudaGetSymbolAddress((void**)&xB, g_xB);
    cudaGetSymbolAddress((void**)&xh, g_xh);
    cudaGetSymbolAddress((void**)&cnt, g_cnt);
    cudaGetSymbolAddress((void**)&rowptr, g_rowptr);
    cudaGetSymbolAddress((void**)&cursor, g_cursor);
    cudaGetSymbolAddress((void**)&bsum, g_bsum);
    cudaGetSymbolAddress((void**)&eidx, g_eidx);
    cudaGetSymbolAddress((void**)&stats, g_stats);
    cudaGetSymbolAddress((void**)&scale, g_scale);
    cudaGetSymbolAddress((void**)&shift, g_shift);
    cudaGetSymbolAddress((void**)&WtB0, g_WtB0);
    cudaGetSymbolAddress((void**)&WtS0, g_WtS0);
    cudaGetSymbolAddress((void**)&WtB1, g_WtB1);
    cudaGetSymbolAddress((void**)&WtS1, g_WtS1);
    cudaGetSymbolAddress((void**)&WtB2, g_WtB2);
    cudaGetSymbolAddress((void**)&WtS2, g_WtS2);

    cudaFuncSetAttribute(gemm_wmma_kernel<64>,
                         cudaFuncAttributeMaxDynamicSharedMemorySize, GEMM_SMEM);
    cudaFuncSetAttribute(gemm_wmma_kernel<128>,
                         cudaFuncAttributeMaxDynamicSharedMemorySize, GEMM_SMEM);

    const int T = 256;
    int gb = (n + 127) / 128;
    int nb = (n + 2047) / 2048;
    int gwarp = (n + 7) / 8;

    // ---- all weight splits + layer-0 fp16 shadow up front ----
    wsplit_kernel<<<(128 * 128 + T - 1) / T, T>>>(Ws0, Wn0, WtB0, WtS0, 64);
    wsplit_kernel<<<(128 * 256 + T - 1) / T, T>>>(Ws1, Wn1, WtB1, WtS1, 128);
    wsplit_kernel<<<(128 * 256 + T - 1) / T, T>>>(Ws2, Wn2, WtB2, WtS2, 128);
    xcvt_kernel<<<(n * 16 + T - 1) / T, T>>>((const float4*)x, (uint2*)xh, n * 16);

    // ---- CSR build (once, reused by all 3 layers) ----
    zero2_kernel<<<(n / 4 + T - 1) / T, T>>>((float4*)cnt, (float4*)cursor, n / 4);
    zero_kernel<<<1, 64>>>((float4*)stats, 64);   // once; bnparam re-zeros after
    count_kernel<<<(E + T - 1) / T, T>>>(dst, cnt, E);
    scan1_kernel<<<nb, 256>>>(cnt, rowptr, bsum, n);
    scan2_kernel<<<1, 32>>>(bsum, nb);
    scan3_kernel<<<(n + T - 1) / T, T>>>(rowptr, bsum, n);
    fill_kernel<<<(E + T - 1) / T, T>>>(src, dst, rowptr, cursor, eidx, E);

    // ---- layer 0 (DIN = 64) ----
    gather_kernel<64><<<gwarp, T>>>(xh, eidx, rowptr, cnt, neigh, n);
    gemm_wmma_kernel<64><<<gb, T, GEMM_SMEM>>>(x, neigh, WtB0, WtS0, b0, h, stats, n);
    bnparam_kernel<<<1, 128>>>(stats, g0, be0, scale, shift, invN);
    bn_relu_kernel<<<(n * 32 + T - 1) / T, T>>>(h, scale, shift, xA, (uint2*)xh, n);

    // ---- layer 1 (DIN = 128) ----
    gather_kernel<128><<<gwarp, T>>>(xh, eidx, rowptr, cnt, neigh, n);
    gemm_wmma_kernel<128><<<gb, T, GEMM_SMEM>>>(xA, neigh, WtB1, WtS1, b1, h, stats, n);
    bnparam_kernel<<<1, 128>>>(stats, g1, be1, scale, shift, invN);
    bn_relu_kernel<<<(n * 32 + T - 1) / T, T>>>(h, scale, shift, xB, (uint2*)xh, n);

    // ---- layer 2 (DIN = 128) + fused BN/ReLU/classifier ----
    gather_kernel<128><<<gwarp, T>>>(xh, eidx, rowptr, cnt, neigh, n);
    gemm_wmma_kernel<128><<<gb, T, GEMM_SMEM>>>(xB, neigh, WtB2, WtS2, b2, h, stats, n);
    bnparam_kernel<<<1, 128>>>(stats, g2, be2, scale, shift, invN);
    bn_cls_kernel<<<(n * 32 + T - 1) / T, T>>>(h, scale, shift, Wc, bc, out, n);
}